// round 7
// baseline (speedup 1.0000x reference)
#include <cuda_runtime.h>
#include <cuda_bf16.h>
#include <cstdint>

#define DIM    1024
#define HEADS  16
#define HD     64
#define BATCH  4
#define SEQ    2048
#define MROWS  (BATCH * SEQ)            // 8192
#define QKV_ELEMS (BATCH * HEADS * SEQ * HD)  // 8388608

// 0.125 * log2(e): folded into Q so softmax is pure exp2
#define SCALE_Q 0.18033688011112042f

// ---------------------------------------------------------------------------
// Scratch (allocation-free rule: __device__ globals) — all bf16 hi/lo pairs
// ---------------------------------------------------------------------------
__device__ __nv_bfloat16 g_Qh[QKV_ELEMS], g_Ql[QKV_ELEMS];   // [b,h,n,d], pre-scaled
__device__ __nv_bfloat16 g_Kh[QKV_ELEMS], g_Kl[QKV_ELEMS];   // [b,h,n,d]
__device__ __nv_bfloat16 g_Vh[QKV_ELEMS], g_Vl[QKV_ELEMS];   // [b,h,d,n] (transposed)
__device__ __nv_bfloat16 g_xh[MROWS * DIM], g_xl[MROWS * DIM];
__device__ __nv_bfloat16 g_wh[3 * DIM * DIM], g_wl[3 * DIM * DIM];  // W^T [n][k]
__device__ __nv_bfloat16 g_woh[DIM * DIM], g_wol[DIM * DIM];        // Wo^T [n][k]
__device__ __nv_bfloat16 g_oh[MROWS * DIM], g_ol[MROWS * DIM];      // attn out [m][h*64+d]

// ---------------------------------------------------------------------------
// helpers
// ---------------------------------------------------------------------------
__device__ __forceinline__ uint32_t smem_u32(const void* p) {
    uint32_t a;
    asm("{ .reg .u64 t; cvta.to.shared.u64 t, %1; cvt.u32.u64 %0, t; }" : "=r"(a) : "l"(p));
    return a;
}
__device__ __forceinline__ void ldsm4(uint32_t& r0, uint32_t& r1, uint32_t& r2, uint32_t& r3,
                                      uint32_t addr) {
    asm volatile("ldmatrix.sync.aligned.m8n8.x4.shared.b16 {%0,%1,%2,%3}, [%4];"
                 : "=r"(r0), "=r"(r1), "=r"(r2), "=r"(r3) : "r"(addr));
}
__device__ __forceinline__ void mma16816(float* d, const uint32_t* a, const uint32_t* b) {
    asm volatile(
        "mma.sync.aligned.m16n8k16.row.col.f32.bf16.bf16.f32 "
        "{%0,%1,%2,%3}, {%4,%5,%6,%7}, {%8,%9}, {%0,%1,%2,%3};"
        : "+f"(d[0]), "+f"(d[1]), "+f"(d[2]), "+f"(d[3])
        : "r"(a[0]), "r"(a[1]), "r"(a[2]), "r"(a[3]), "r"(b[0]), "r"(b[1]));
}
__device__ __forceinline__ void cp16(uint32_t saddr, const void* gptr) {
    asm volatile("cp.async.cg.shared.global [%0], [%1], 16;" :: "r"(saddr), "l"(gptr));
}
__device__ __forceinline__ void cp_commit() {
    asm volatile("cp.async.commit_group;" ::: "memory");
}
__device__ __forceinline__ void cp_wait0() {
    asm volatile("cp.async.wait_group 0;" ::: "memory");
}
__device__ __forceinline__ void split2(float v, __nv_bfloat16& h, __nv_bfloat16& l) {
    h = __float2bfloat16(v);
    l = __float2bfloat16(v - __bfloat162float(h));
}
__device__ __forceinline__ uint32_t packbf(__nv_bfloat16 a, __nv_bfloat16 b) {
    __nv_bfloat162 t = {a, b};
    return *(uint32_t*)&t;
}
__device__ __forceinline__ void split_pack(float v0, float v1, uint32_t& ph, uint32_t& pl) {
    __nv_bfloat16 h0, l0, h1, l1;
    split2(v0, h0, l0); split2(v1, h1, l1);
    ph = packbf(h0, h1);
    pl = packbf(l0, l1);
}

// ---------------------------------------------------------------------------
// Prep kernels
// ---------------------------------------------------------------------------
__global__ __launch_bounds__(256) void split_x_kernel(const float* __restrict__ x) {
    int i = (blockIdx.x * 256 + threadIdx.x) * 4;
    float4 v = *(const float4*)(x + i);
    __nv_bfloat16 h0, h1, h2, h3, l0, l1, l2, l3;
    split2(v.x, h0, l0); split2(v.y, h1, l1); split2(v.z, h2, l2); split2(v.w, h3, l3);
    *(__nv_bfloat162*)(g_xh + i)     = {h0, h1};
    *(__nv_bfloat162*)(g_xh + i + 2) = {h2, h3};
    *(__nv_bfloat162*)(g_xl + i)     = {l0, l1};
    *(__nv_bfloat162*)(g_xl + i + 2) = {l2, l3};
}

__global__ __launch_bounds__(256) void transpose_split4(const float* __restrict__ W0,
                                                        const float* __restrict__ W1,
                                                        const float* __restrict__ W2,
                                                        const float* __restrict__ W3) {
    __shared__ float t[32][33];
    const int z = blockIdx.z;
    const float* src = (z == 0) ? W0 : (z == 1) ? W1 : (z == 2) ? W2 : W3;
    __nv_bfloat16* dh = (z < 3) ? (g_wh + (size_t)z * DIM * DIM) : g_woh;
    __nv_bfloat16* dl = (z < 3) ? (g_wl + (size_t)z * DIM * DIM) : g_wol;

    const int bx = blockIdx.x * 32;
    const int by = blockIdx.y * 32;
    const int x = threadIdx.x, y0 = threadIdx.y;
#pragma unroll
    for (int i = 0; i < 32; i += 8)
        t[y0 + i][x] = src[(by + y0 + i) * DIM + bx + x];
    __syncthreads();
#pragma unroll
    for (int i = 0; i < 32; i += 8) {
        float v = t[x][y0 + i];
        __nv_bfloat16 h, l; split2(v, h, l);
        int o = (bx + y0 + i) * DIM + by + x;
        dh[o] = h; dl[o] = l;
    }
}

// ---------------------------------------------------------------------------
// bf16x3 split GEMM, cp.async 2-stage pipeline, BK=32, 2 CTAs/SM.
// MODE 0: QKV -> Q (pre-scaled) / K ([b,h,n,d]) and V^T ([b,h,d,n])
// MODE 1: out proj + bias -> d_out (fp32)
// ---------------------------------------------------------------------------
#define GBK    32
#define GSTR   40
#define GARR   (128 * GSTR)
#define GSTAGE (4 * GARR)
#define GSM_BYTES (2 * GSTAGE * 2)     // 81920

template <int MODE>
__global__ __launch_bounds__(256, 2) void gemm_mma(
    const __nv_bfloat16* __restrict__ Ah, const __nv_bfloat16* __restrict__ Al,
    const __nv_bfloat16* __restrict__ Bh, const __nv_bfloat16* __restrict__ Bl,
    float* __restrict__ outp, const float* __restrict__ bo) {
    extern __shared__ __nv_bfloat16 sm[];

    const int tid  = threadIdx.x;
    const int lane = tid & 31;
    const int wid  = tid >> 5;
    const int wm   = wid & 1;
    const int wn   = wid >> 1;
    const int row0 = blockIdx.y * 128;
    const int col0 = blockIdx.x * 128;

    const __nv_bfloat16* pAh = Ah + (size_t)row0 * DIM;
    const __nv_bfloat16* pAl = Al + (size_t)row0 * DIM;
    const __nv_bfloat16* pBh = Bh + (size_t)col0 * DIM;
    const __nv_bfloat16* pBl = Bl + (size_t)col0 * DIM;

    const uint32_t sbase = smem_u32(sm);

    float acc[4][4][4];
#pragma unroll
    for (int i = 0; i < 4; i++)
#pragma unroll
        for (int j = 0; j < 4; j++)
#pragma unroll
            for (int q = 0; q < 4; q++) acc[i][j][q] = 0.0f;

    const int a_row = (lane & 15);
    const int a_kof = (lane >> 4) << 3;
    const int b_rof = ((lane >> 4) << 3) + (lane & 7);
    const int b_kof = ((lane >> 3) & 1) << 3;

    auto issue = [&](int c, int st) {
        const int k0 = c * GBK;
        const uint32_t sst = sbase + (uint32_t)(st * GSTAGE) * 2;
#pragma unroll
        for (int it = 0; it < 2; ++it) {
            const int lin = it * 256 + tid;   // 0..511 : 128 rows x 4 groups
            const int rr = lin >> 2;
            const int cg = (lin & 3) * 8;
            const uint32_t so = (uint32_t)(rr * GSTR + cg) * 2;
            const size_t go = (size_t)rr * DIM + k0 + cg;
            cp16(sst + so,                            pAh + go);
            cp16(sst + (uint32_t)GARR * 2 + so,       pAl + go);
            cp16(sst + (uint32_t)(2 * GARR) * 2 + so, pBh + go);
            cp16(sst + (uint32_t)(3 * GARR) * 2 + so, pBl + go);
        }
        cp_commit();
    };

    issue(0, 0);

    const int NC = DIM / GBK;   // 32
    for (int c = 0; c < NC; ++c) {
        const int st = c & 1;
        cp_wait0();
        __syncthreads();
        if (c + 1 < NC) issue(c + 1, st ^ 1);

        const uint32_t sA = sbase + (uint32_t)(st * GSTAGE) * 2;
        const uint32_t sAh = sA;
        const uint32_t sAl = sA + (uint32_t)GARR * 2;
        const uint32_t sBh = sA + (uint32_t)(2 * GARR) * 2;
        const uint32_t sBl = sA + (uint32_t)(3 * GARR) * 2;

#pragma unroll
        for (int ks = 0; ks < GBK / 16; ++ks) {
            uint32_t bh[2][4], bl[2][4];
#pragma unroll
            for (int p = 0; p < 2; ++p) {
                const uint32_t off =
                    (uint32_t)(((wn * 32 + p * 16 + b_rof) * GSTR + ks * 16 + b_kof) * 2);
                ldsm4(bh[p][0], bh[p][1], bh[p][2], bh[p][3], sBh + off);
                ldsm4(bl[p][0], bl[p][1], bl[p][2], bl[p][3], sBl + off);
            }
#pragma unroll
            for (int mi = 0; mi < 4; ++mi) {
                uint32_t ah[4], al[4];
                const uint32_t off =
                    (uint32_t)(((wm * 64 + mi * 16 + a_row) * GSTR + ks * 16 + a_kof) * 2);
                ldsm4(ah[0], ah[1], ah[2], ah[3], sAh + off);
                ldsm4(al[0], al[1], al[2], al[3], sAl + off);
#pragma unroll
                for (int p = 0; p < 2; ++p)
#pragma unroll
                    for (int q = 0; q < 2; ++q) {
                        float* d = acc[mi][p * 2 + q];
                        mma16816(d, ah, &bh[p][q * 2]);
                        mma16816(d, ah, &bl[p][q * 2]);
                        mma16816(d, al, &bh[p][q * 2]);
                    }
            }
        }
    }

#pragma unroll
    for (int mi = 0; mi < 4; ++mi) {
#pragma unroll
        for (int nj = 0; nj < 4; ++nj) {
            const int r = row0 + wm * 64 + mi * 16 + (lane >> 2);
            const int cgl = col0 + wn * 32 + nj * 8 + (lane & 3) * 2;
#pragma unroll
            for (int half = 0; half < 2; ++half) {
                const int rr = r + half * 8;
                float v0 = acc[mi][nj][half * 2 + 0];
                float v1 = acc[mi][nj][half * 2 + 1];
                if (MODE == 0) {
                    const int b_ = rr >> 11, n = rr & 2047;
                    const int wsel = cgl >> 10;
                    const int c1 = cgl & 1023;
                    const int h = c1 >> 6, d0 = c1 & 63;
                    if (wsel == 0) { v0 *= SCALE_Q; v1 *= SCALE_Q; }
                    __nv_bfloat16 h0, l0, h1, l1;
                    split2(v0, h0, l0); split2(v1, h1, l1);
                    if (wsel < 2) {
                        __nv_bfloat16* dh = wsel ? g_Kh : g_Qh;
                        __nv_bfloat16* dl = wsel ? g_Kl : g_Ql;
                        const size_t o = ((size_t)(b_ * HEADS + h) * SEQ + n) * HD + d0;
                        *(__nv_bfloat162*)(dh + o) = {h0, h1};
                        *(__nv_bfloat162*)(dl + o) = {l0, l1};
                    } else {
                        const size_t o = ((size_t)(b_ * HEADS + h) * HD + d0) * SEQ + n;
                        g_Vh[o] = h0; g_Vh[o + SEQ] = h1;
                        g_Vl[o] = l0; g_Vl[o + SEQ] = l1;
                    }
                } else {
                    *(float2*)(outp + (size_t)rr * DIM + cgl) =
                        make_float2(v0 + bo[cgl], v1 + bo[cgl + 1]);
                }
            }
        }
    }
}

// ---------------------------------------------------------------------------
// Flash attention: 128-thread CTAs (4 warps x 16 q-rows = 64 q rows),
// KV chunk 32, cp.async 2-stage, Q fragments in registers, 4 CTAs/SM.
// ---------------------------------------------------------------------------
#define KSTR 72                       // K array row stride (elems), 32 rows
#define VSTR 40                       // V^T array row stride (elems), 64 rows
#define K_AR (32 * KSTR)              // 2304 elems
#define V_AR (64 * VSTR)              // 2560 elems
#define AST_EL (2 * K_AR + 2 * V_AR)  // 9728 elems per stage
// stage elem offsets
#define OF_KH 0
#define OF_KL K_AR
#define OF_VH (2 * K_AR)
#define OF_VL (2 * K_AR + V_AR)
#define A2_TOTAL (2 * AST_EL * 2)     // 38912 bytes

__global__ __launch_bounds__(128, 4) void attn_mma() {
    extern __shared__ __nv_bfloat16 sma[];

    const int bh   = blockIdx.y;
    const int rblk = blockIdx.x;       // 0..31 (64-row q tiles)
    const int tid  = threadIdx.x;
    const int lane = tid & 31;
    const int wid  = tid >> 5;         // 0..3
    const int q0   = wid * 16;

    const size_t qbase = ((size_t)bh * SEQ + rblk * 64) * HD;
    const size_t kbase = (size_t)bh * SEQ * HD;
    const size_t vbase = (size_t)bh * HD * SEQ;

    const uint32_t sbase = smem_u32(sma);

    const int a_row = lane & 15;
    const int a_kof = (lane >> 4) << 3;
    const int b_rof = ((lane >> 4) << 3) + (lane & 7);
    const int b_kof = ((lane >> 3) & 1) << 3;

    // ---- stage Q (64x64 hi/lo) into stage-0 smem, then to registers ----
#pragma unroll
    for (int it = 0; it < 4; ++it) {
        const int lin = it * 128 + tid;        // 0..511 : 64 rows x 8 groups
        const int r = lin >> 3, d = (lin & 7) * 8;
        const uint32_t so = (uint32_t)(r * KSTR + d) * 2;
        cp16(sbase + so,                         g_Qh + qbase + (size_t)r * HD + d);
        cp16(sbase + (uint32_t)(64 * KSTR) * 2 + so, g_Ql + qbase + (size_t)r * HD + d);
    }
    cp_commit();
    cp_wait0();
    __syncthreads();

    uint32_t qh[4][4], ql[4][4];
#pragma unroll
    for (int ks = 0; ks < 4; ++ks) {
        const uint32_t off = (uint32_t)(((q0 + a_row) * KSTR + ks * 16 + a_kof) * 2);
        ldsm4(qh[ks][0], qh[ks][1], qh[ks][2], qh[ks][3], sbase + off);
        ldsm4(ql[ks][0], ql[ks][1], ql[ks][2], ql[ks][3],
              sbase + (uint32_t)(64 * KSTR) * 2 + off);
    }
    __syncthreads();   // all warps done reading Q staging before KV overwrites

    auto issue_kv = [&](int chunk, int st) {
        const int c0 = chunk * 32;
        const uint32_t skv = sbase + (uint32_t)(st * AST_EL) * 2;
        // K: 32 rows x 8 groups (2 iters of 128 threads)
#pragma unroll
        for (int it = 0; it < 2; ++it) {
            const int lin = it * 128 + tid;
            const int r = lin >> 3, d = (lin & 7) * 8;
            const uint32_t so = (uint32_t)(r * KSTR + d) * 2;
            cp16(skv + (uint32_t)OF_KH * 2 + so, g_Kh + kbase + (size_t)(c0 + r) * HD + d);
            cp16(skv + (uint32_t)OF_KL * 2 + so, g_Kl + kbase + (size_t)(c0 + r) * HD + d);
        }
        // V^T: 64 rows x 4 groups (2 iters)
#pragma unroll
        for (int it = 0; it < 2; ++it) {
            const int lin = it * 128 + tid;
            const int r = lin >> 2, d = (lin & 3) * 8;
            const uint32_t so = (uint32_t)(r * VSTR + d) * 2;
            cp16(skv + (uint32_t)OF_VH * 2 + so, g_Vh + vbase + (size_t)r * SEQ + c0 + d);
            cp16(skv + (uint32_t)OF_VL * 2 + so, g_Vl + vbase + (size_t)r * SEQ + c0 + d);
        }
        cp_commit();
    };

    issue_kv(0, 0);

    float acc_o[8][4];
#pragma unroll
    for (int j = 0; j < 8; j++)
#pragma unroll
        for (int q = 0; q < 4; q++) acc_o[j][q] = 0.0f;
    float mi[2] = {-1e30f, -1e30f}, li[2] = {0.0f, 0.0f};

    const int NC = SEQ / 32;   // 64
    for (int c = 0; c < NC; ++c) {
        const int st = c & 1;
        cp_wait0();
        __syncthreads();
        if (c + 1 < NC) issue_kv(c + 1, st ^ 1);

        const uint32_t skv = sbase + (uint32_t)(st * AST_EL) * 2;
        const uint32_t uKh = skv + (uint32_t)OF_KH * 2;
        const uint32_t uKl = skv + (uint32_t)OF_KL * 2;
        const uint32_t uVh = skv + (uint32_t)OF_VH * 2;
        const uint32_t uVl = skv + (uint32_t)OF_VL * 2;

        // --- S = Q K^T (16 q rows x 32 kv) ---
        float acc_s[4][4];
#pragma unroll
        for (int j = 0; j < 4; j++)
#pragma unroll
            for (int q = 0; q < 4; q++) acc_s[j][q] = 0.0f;

#pragma unroll
        for (int ks = 0; ks < 4; ++ks) {
#pragma unroll
            for (int p = 0; p < 2; ++p) {
                uint32_t kh_[4], kl_[4];
                const uint32_t off = (uint32_t)(((p * 16 + b_rof) * KSTR + ks * 16 + b_kof) * 2);
                ldsm4(kh_[0], kh_[1], kh_[2], kh_[3], uKh + off);
                ldsm4(kl_[0], kl_[1], kl_[2], kl_[3], uKl + off);
#pragma unroll
                for (int q = 0; q < 2; ++q) {
                    float* d = acc_s[p * 2 + q];
                    mma16816(d, qh[ks], &kh_[q * 2]);
                    mma16816(d, qh[ks], &kl_[q * 2]);
                    mma16816(d, ql[ks], &kh_[q * 2]);
                }
            }
        }

        // --- online softmax in log2 domain (scale pre-folded into Q) ---
#pragma unroll
        for (int half = 0; half < 2; ++half) {
            float rmax = -1e30f;
#pragma unroll
            for (int nj = 0; nj < 4; ++nj)
#pragma unroll
                for (int t = 0; t < 2; ++t)
                    rmax = fmaxf(rmax, acc_s[nj][half * 2 + t]);
            rmax = fmaxf(rmax, __shfl_xor_sync(0xffffffffu, rmax, 1));
            rmax = fmaxf(rmax, __shfl_xor_sync(0xffffffffu, rmax, 2));
            const float mn = fmaxf(mi[half], rmax);
            float rsum = 0.0f;
#pragma unroll
            for (int nj = 0; nj < 4; ++nj)
#pragma unroll
                for (int t = 0; t < 2; ++t) {
                    const float e = exp2f(acc_s[nj][half * 2 + t] - mn);
                    acc_s[nj][half * 2 + t] = e;
                    rsum += e;
                }
            rsum += __shfl_xor_sync(0xffffffffu, rsum, 1);
            rsum += __shfl_xor_sync(0xffffffffu, rsum, 2);
            const float alpha = exp2f(mi[half] - mn);
            li[half] = li[half] * alpha + rsum;
            mi[half] = mn;
#pragma unroll
            for (int nj = 0; nj < 8; ++nj)
#pragma unroll
                for (int t = 0; t < 2; ++t) acc_o[nj][half * 2 + t] *= alpha;
        }

        // --- O += P V (P frags from registers) ---
#pragma unroll
        for (int ks2 = 0; ks2 < 2; ++ks2) {
            uint32_t ph[4], pl[4];
            split_pack(acc_s[2 * ks2][0],     acc_s[2 * ks2][1],     ph[0], pl[0]);
            split_pack(acc_s[2 * ks2][2],     acc_s[2 * ks2][3],     ph[1], pl[1]);
            split_pack(acc_s[2 * ks2 + 1][0], acc_s[2 * ks2 + 1][1], ph[2], pl[2]);
            split_pack(acc_s[2 * ks2 + 1][2], acc_s[2 * ks2 + 1][3], ph[3], pl[3]);
#pragma unroll
            for (int p = 0; p < 4; ++p) {
                uint32_t vh_[4], vl_[4];
                const uint32_t off = (uint32_t)(((p * 16 + b_rof) * VSTR + ks2 * 16 + b_kof) * 2);
                ldsm4(vh_[0], vh_[1], vh_[2], vh_[3], uVh + off);
                ldsm4(vl_[0], vl_[1], vl_[2], vl_[3], uVl + off);
#pragma unroll
                for (int q = 0; q < 2; ++q) {
                    float* d = acc_o[p * 2 + q];
                    mma16816(d, ph, &vh_[q * 2]);
                    mma16816(d, ph, &vl_[q * 2]);
                    mma16816(d, pl, &vh_[q * 2]);
                }
            }
        }
    }

    // Epilogue
    const int b_ = bh >> 4, h = bh & 15;
#pragma unroll
    for (int half = 0; half < 2; ++half) {
        const float inv = 1.0f / li[half];
        const int row = rblk * 64 + q0 + (lane >> 2) + half * 8;
        const size_t mrow = ((size_t)b_ * SEQ + row) * DIM + h * HD;
#pragma unroll
        for (int nj = 0; nj < 8; ++nj) {
            const float o0 = acc_o[nj][half * 2 + 0] * inv;
            const float o1 = acc_o[nj][half * 2 + 1] * inv;
            __nv_bfloat16 h0, l0, h1, l1;
            split2(o0, h0, l0); split2(o1, h1, l1);
            const int cc = nj * 8 + (lane & 3) * 2;
            *(__nv_bfloat162*)(g_oh + mrow + cc) = {h0, h1};
            *(__nv_bfloat162*)(g_ol + mrow + cc) = {l0, l1};
        }
    }
}

// ---------------------------------------------------------------------------

extern "C" void kernel_launch(void* const* d_in, const int* in_sizes, int n_in,
                              void* d_out, int out_size) {
    (void)in_sizes; (void)n_in; (void)out_size;
    const float* x  = (const float*)d_in[0];
    const float* Wq = (const float*)d_in[1];
    const float* Wk = (const float*)d_in[2];
    const float* Wv = (const float*)d_in[3];
    const float* Wo = (const float*)d_in[4];
    const float* bo = (const float*)d_in[5];
    float* out = (float*)d_out;

    cudaFuncSetAttribute(gemm_mma<0>, cudaFuncAttributeMaxDynamicSharedMemorySize, GSM_BYTES);
    cudaFuncSetAttribute(gemm_mma<1>, cudaFuncAttributeMaxDynamicSharedMemorySize, GSM_BYTES);
    cudaFuncSetAttribute(attn_mma,    cudaFuncAttributeMaxDynamicSharedMemorySize, A2_TOTAL);

    __nv_bfloat16 *wh, *wl, *woh, *wol, *xh, *xl, *oh, *ol;
    cudaGetSymbolAddress((void**)&wh,  g_wh);
    cudaGetSymbolAddress((void**)&wl,  g_wl);
    cudaGetSymbolAddress((void**)&woh, g_woh);
    cudaGetSymbolAddress((void**)&wol, g_wol);
    cudaGetSymbolAddress((void**)&xh,  g_xh);
    cudaGetSymbolAddress((void**)&xl,  g_xl);
    cudaGetSymbolAddress((void**)&oh,  g_oh);
    cudaGetSymbolAddress((void**)&ol,  g_ol);

    split_x_kernel<<<MROWS * DIM / 1024, 256>>>(x);
    transpose_split4<<<dim3(32, 32, 4), dim3(32, 8)>>>(Wq, Wk, Wv, Wo);

    gemm_mma<0><<<dim3(24, 64), 256, GSM_BYTES>>>(xh, xl, wh, wl, nullptr, nullptr);
    attn_mma<<<dim3(32, 64), 128, A2_TOTAL>>>();
    gemm_mma<1><<<dim3(8, 64), 256, GSM_BYTES>>>(oh, ol, woh, wol, out, bo);
}

// round 8
// speedup vs baseline: 1.0315x; 1.0315x over previous
#include <cuda_runtime.h>
#include <cuda_bf16.h>
#include <cstdint>

#define DIM    1024
#define HEADS  16
#define HD     64
#define BATCH  4
#define SEQ    2048
#define MROWS  (BATCH * SEQ)            // 8192
#define QKV_ELEMS (BATCH * HEADS * SEQ * HD)  // 8388608

// 0.125 * log2(e): folded into Q so softmax is pure exp2
#define SCALE_Q 0.18033688011112042f

// ---------------------------------------------------------------------------
// Scratch (allocation-free rule: __device__ globals) — all bf16 hi/lo pairs
// ---------------------------------------------------------------------------
__device__ __nv_bfloat16 g_Qh[QKV_ELEMS], g_Ql[QKV_ELEMS];   // [b,h,n,d], pre-scaled
__device__ __nv_bfloat16 g_Kh[QKV_ELEMS], g_Kl[QKV_ELEMS];   // [b,h,n,d]
__device__ __nv_bfloat16 g_Vh[QKV_ELEMS], g_Vl[QKV_ELEMS];   // [b,h,d,n] (transposed)
__device__ __nv_bfloat16 g_xh[MROWS * DIM], g_xl[MROWS * DIM];
__device__ __nv_bfloat16 g_wh[3 * DIM * DIM], g_wl[3 * DIM * DIM];  // W^T [n][k]
__device__ __nv_bfloat16 g_woh[DIM * DIM], g_wol[DIM * DIM];        // Wo^T [n][k]
__device__ __nv_bfloat16 g_oh[MROWS * DIM], g_ol[MROWS * DIM];      // attn out [m][h*64+d]

// ---------------------------------------------------------------------------
// helpers
// ---------------------------------------------------------------------------
__device__ __forceinline__ uint32_t smem_u32(const void* p) {
    uint32_t a;
    asm("{ .reg .u64 t; cvta.to.shared.u64 t, %1; cvt.u32.u64 %0, t; }" : "=r"(a) : "l"(p));
    return a;
}
__device__ __forceinline__ void ldsm4(uint32_t& r0, uint32_t& r1, uint32_t& r2, uint32_t& r3,
                                      uint32_t addr) {
    asm volatile("ldmatrix.sync.aligned.m8n8.x4.shared.b16 {%0,%1,%2,%3}, [%4];"
                 : "=r"(r0), "=r"(r1), "=r"(r2), "=r"(r3) : "r"(addr));
}
__device__ __forceinline__ void mma16816(float* d, const uint32_t* a, const uint32_t* b) {
    asm volatile(
        "mma.sync.aligned.m16n8k16.row.col.f32.bf16.bf16.f32 "
        "{%0,%1,%2,%3}, {%4,%5,%6,%7}, {%8,%9}, {%0,%1,%2,%3};"
        : "+f"(d[0]), "+f"(d[1]), "+f"(d[2]), "+f"(d[3])
        : "r"(a[0]), "r"(a[1]), "r"(a[2]), "r"(a[3]), "r"(b[0]), "r"(b[1]));
}
__device__ __forceinline__ void cp16(uint32_t saddr, const void* gptr) {
    asm volatile("cp.async.cg.shared.global [%0], [%1], 16;" :: "r"(saddr), "l"(gptr));
}
__device__ __forceinline__ void cp_commit() {
    asm volatile("cp.async.commit_group;" ::: "memory");
}
__device__ __forceinline__ void cp_wait0() {
    asm volatile("cp.async.wait_group 0;" ::: "memory");
}
__device__ __forceinline__ void split2(float v, __nv_bfloat16& h, __nv_bfloat16& l) {
    h = __float2bfloat16(v);
    l = __float2bfloat16(v - __bfloat162float(h));
}
__device__ __forceinline__ uint32_t packbf(__nv_bfloat16 a, __nv_bfloat16 b) {
    __nv_bfloat162 t = {a, b};
    return *(uint32_t*)&t;
}
__device__ __forceinline__ void split_pack(float v0, float v1, uint32_t& ph, uint32_t& pl) {
    __nv_bfloat16 h0, l0, h1, l1;
    split2(v0, h0, l0); split2(v1, h1, l1);
    ph = packbf(h0, h1);
    pl = packbf(l0, l1);
}

// ---------------------------------------------------------------------------
// Prep kernels
// ---------------------------------------------------------------------------
__global__ __launch_bounds__(256) void split_x_kernel(const float* __restrict__ x) {
    int i = (blockIdx.x * 256 + threadIdx.x) * 4;
    float4 v = *(const float4*)(x + i);
    __nv_bfloat16 h0, h1, h2, h3, l0, l1, l2, l3;
    split2(v.x, h0, l0); split2(v.y, h1, l1); split2(v.z, h2, l2); split2(v.w, h3, l3);
    *(__nv_bfloat162*)(g_xh + i)     = {h0, h1};
    *(__nv_bfloat162*)(g_xh + i + 2) = {h2, h3};
    *(__nv_bfloat162*)(g_xl + i)     = {l0, l1};
    *(__nv_bfloat162*)(g_xl + i + 2) = {l2, l3};
}

__global__ __launch_bounds__(256) void transpose_split4(const float* __restrict__ W0,
                                                        const float* __restrict__ W1,
                                                        const float* __restrict__ W2,
                                                        const float* __restrict__ W3) {
    __shared__ float t[32][33];
    const int z = blockIdx.z;
    const float* src = (z == 0) ? W0 : (z == 1) ? W1 : (z == 2) ? W2 : W3;
    __nv_bfloat16* dh = (z < 3) ? (g_wh + (size_t)z * DIM * DIM) : g_woh;
    __nv_bfloat16* dl = (z < 3) ? (g_wl + (size_t)z * DIM * DIM) : g_wol;

    const int bx = blockIdx.x * 32;
    const int by = blockIdx.y * 32;
    const int x = threadIdx.x, y0 = threadIdx.y;
#pragma unroll
    for (int i = 0; i < 32; i += 8)
        t[y0 + i][x] = src[(by + y0 + i) * DIM + bx + x];
    __syncthreads();
#pragma unroll
    for (int i = 0; i < 32; i += 8) {
        float v = t[x][y0 + i];
        __nv_bfloat16 h, l; split2(v, h, l);
        int o = (bx + y0 + i) * DIM + by + x;
        dh[o] = h; dl[o] = l;
    }
}

// ---------------------------------------------------------------------------
// bf16x3 split GEMM, cp.async 2-stage pipeline, BK=32, 2 CTAs/SM.
// MODE 0: QKV -> Q (pre-scaled) / K ([b,h,n,d]) and V^T ([b,h,d,n])
// MODE 1: out proj + bias -> d_out (fp32)
// ---------------------------------------------------------------------------
#define GBK    32
#define GSTR   40
#define GARR   (128 * GSTR)
#define GSTAGE (4 * GARR)
#define GSM_BYTES (2 * GSTAGE * 2)     // 81920

template <int MODE>
__global__ __launch_bounds__(256, 2) void gemm_mma(
    const __nv_bfloat16* __restrict__ Ah, const __nv_bfloat16* __restrict__ Al,
    const __nv_bfloat16* __restrict__ Bh, const __nv_bfloat16* __restrict__ Bl,
    float* __restrict__ outp, const float* __restrict__ bo) {
    extern __shared__ __nv_bfloat16 sm[];

    const int tid  = threadIdx.x;
    const int lane = tid & 31;
    const int wid  = tid >> 5;
    const int wm   = wid & 1;
    const int wn   = wid >> 1;
    const int row0 = blockIdx.y * 128;
    const int col0 = blockIdx.x * 128;

    const __nv_bfloat16* pAh = Ah + (size_t)row0 * DIM;
    const __nv_bfloat16* pAl = Al + (size_t)row0 * DIM;
    const __nv_bfloat16* pBh = Bh + (size_t)col0 * DIM;
    const __nv_bfloat16* pBl = Bl + (size_t)col0 * DIM;

    const uint32_t sbase = smem_u32(sm);

    float acc[4][4][4];
#pragma unroll
    for (int i = 0; i < 4; i++)
#pragma unroll
        for (int j = 0; j < 4; j++)
#pragma unroll
            for (int q = 0; q < 4; q++) acc[i][j][q] = 0.0f;

    const int a_row = (lane & 15);
    const int a_kof = (lane >> 4) << 3;
    const int b_rof = ((lane >> 4) << 3) + (lane & 7);
    const int b_kof = ((lane >> 3) & 1) << 3;

    auto issue = [&](int c, int st) {
        const int k0 = c * GBK;
        const uint32_t sst = sbase + (uint32_t)(st * GSTAGE) * 2;
#pragma unroll
        for (int it = 0; it < 2; ++it) {
            const int lin = it * 256 + tid;   // 0..511 : 128 rows x 4 groups
            const int rr = lin >> 2;
            const int cg = (lin & 3) * 8;
            const uint32_t so = (uint32_t)(rr * GSTR + cg) * 2;
            const size_t go = (size_t)rr * DIM + k0 + cg;
            cp16(sst + so,                            pAh + go);
            cp16(sst + (uint32_t)GARR * 2 + so,       pAl + go);
            cp16(sst + (uint32_t)(2 * GARR) * 2 + so, pBh + go);
            cp16(sst + (uint32_t)(3 * GARR) * 2 + so, pBl + go);
        }
        cp_commit();
    };

    issue(0, 0);

    const int NC = DIM / GBK;   // 32
    for (int c = 0; c < NC; ++c) {
        const int st = c & 1;
        cp_wait0();
        __syncthreads();
        if (c + 1 < NC) issue(c + 1, st ^ 1);

        const uint32_t sA = sbase + (uint32_t)(st * GSTAGE) * 2;
        const uint32_t sAh = sA;
        const uint32_t sAl = sA + (uint32_t)GARR * 2;
        const uint32_t sBh = sA + (uint32_t)(2 * GARR) * 2;
        const uint32_t sBl = sA + (uint32_t)(3 * GARR) * 2;

#pragma unroll
        for (int ks = 0; ks < GBK / 16; ++ks) {
            uint32_t bh[2][4], bl[2][4];
#pragma unroll
            for (int p = 0; p < 2; ++p) {
                const uint32_t off =
                    (uint32_t)(((wn * 32 + p * 16 + b_rof) * GSTR + ks * 16 + b_kof) * 2);
                ldsm4(bh[p][0], bh[p][1], bh[p][2], bh[p][3], sBh + off);
                ldsm4(bl[p][0], bl[p][1], bl[p][2], bl[p][3], sBl + off);
            }
#pragma unroll
            for (int mi = 0; mi < 4; ++mi) {
                uint32_t ah[4], al[4];
                const uint32_t off =
                    (uint32_t)(((wm * 64 + mi * 16 + a_row) * GSTR + ks * 16 + a_kof) * 2);
                ldsm4(ah[0], ah[1], ah[2], ah[3], sAh + off);
                ldsm4(al[0], al[1], al[2], al[3], sAl + off);
#pragma unroll
                for (int p = 0; p < 2; ++p)
#pragma unroll
                    for (int q = 0; q < 2; ++q) {
                        float* d = acc[mi][p * 2 + q];
                        mma16816(d, ah, &bh[p][q * 2]);
                        mma16816(d, ah, &bl[p][q * 2]);
                        mma16816(d, al, &bh[p][q * 2]);
                    }
            }
        }
    }

#pragma unroll
    for (int mi = 0; mi < 4; ++mi) {
#pragma unroll
        for (int nj = 0; nj < 4; ++nj) {
            const int r = row0 + wm * 64 + mi * 16 + (lane >> 2);
            const int cgl = col0 + wn * 32 + nj * 8 + (lane & 3) * 2;
#pragma unroll
            for (int half = 0; half < 2; ++half) {
                const int rr = r + half * 8;
                float v0 = acc[mi][nj][half * 2 + 0];
                float v1 = acc[mi][nj][half * 2 + 1];
                if (MODE == 0) {
                    const int b_ = rr >> 11, n = rr & 2047;
                    const int wsel = cgl >> 10;
                    const int c1 = cgl & 1023;
                    const int h = c1 >> 6, d0 = c1 & 63;
                    if (wsel == 0) { v0 *= SCALE_Q; v1 *= SCALE_Q; }
                    __nv_bfloat16 h0, l0, h1, l1;
                    split2(v0, h0, l0); split2(v1, h1, l1);
                    if (wsel < 2) {
                        __nv_bfloat16* dh = wsel ? g_Kh : g_Qh;
                        __nv_bfloat16* dl = wsel ? g_Kl : g_Ql;
                        const size_t o = ((size_t)(b_ * HEADS + h) * SEQ + n) * HD + d0;
                        *(__nv_bfloat162*)(dh + o) = {h0, h1};
                        *(__nv_bfloat162*)(dl + o) = {l0, l1};
                    } else {
                        const size_t o = ((size_t)(b_ * HEADS + h) * HD + d0) * SEQ + n;
                        g_Vh[o] = h0; g_Vh[o + SEQ] = h1;
                        g_Vl[o] = l0; g_Vl[o + SEQ] = l1;
                    }
                } else {
                    *(float2*)(outp + (size_t)rr * DIM + cgl) =
                        make_float2(v0 + bo[cgl], v1 + bo[cgl + 1]);
                }
            }
        }
    }
}

// ---------------------------------------------------------------------------
// Flash attention on mma.sync, bf16x3 split, cp.async 2-stage KV pipeline,
// P kept entirely in registers. R6 shape: 256 thr, 8 warps x 16 q-rows,
// KV chunk 64, 2 CTAs/SM. Q pre-scaled; softmax in exp2 domain.
// ---------------------------------------------------------------------------
#define ASTR   72
#define AQ_ELE (128 * ASTR)            // 9216 per Q array
#define AKV_AR (64 * ASTR)             // 4608 per KV array
#define AKV_ST (4 * AKV_AR)            // 18432 per stage
#define A_KV0  (2 * AQ_ELE)            // 18432
#define A_TOTAL ((A_KV0 + 2 * AKV_ST) * 2)   // 110592 bytes

__global__ __launch_bounds__(256, 2) void attn_mma() {
    extern __shared__ __nv_bfloat16 sma[];

    const int bh   = blockIdx.y;
    const int rblk = blockIdx.x;
    const int tid  = threadIdx.x;
    const int lane = tid & 31;
    const int wid  = tid >> 5;
    const int q0   = wid * 16;

    const size_t qbase = ((size_t)bh * SEQ + rblk * 128) * HD;
    const size_t kbase = (size_t)bh * SEQ * HD;
    const size_t vbase = (size_t)bh * HD * SEQ;

    const uint32_t sbase = smem_u32(sma);
    const uint32_t uQh = sbase;
    const uint32_t uQl = sbase + (uint32_t)AQ_ELE * 2;

    // Q tile 128x64 hi/lo via cp.async
#pragma unroll
    for (int it = 0; it < 4; ++it) {
        const int lin = it * 256 + tid;
        const int r = lin >> 3, d = (lin & 7) * 8;
        const uint32_t so = (uint32_t)(r * ASTR + d) * 2;
        cp16(uQh + so, g_Qh + qbase + (size_t)r * HD + d);
        cp16(uQl + so, g_Ql + qbase + (size_t)r * HD + d);
    }
    cp_commit();

    auto issue_kv = [&](int chunk, int st) {
        const int c0 = chunk * 64;
        const uint32_t skv = sbase + (uint32_t)(A_KV0 + st * AKV_ST) * 2;
#pragma unroll
        for (int it = 0; it < 2; ++it) {
            const int lin = it * 256 + tid;
            const int r = lin >> 3, d = (lin & 7) * 8;
            const uint32_t so = (uint32_t)(r * ASTR + d) * 2;
            cp16(skv + so,                              g_Kh + kbase + (size_t)(c0 + r) * HD + d);
            cp16(skv + (uint32_t)AKV_AR * 2 + so,       g_Kl + kbase + (size_t)(c0 + r) * HD + d);
            cp16(skv + (uint32_t)(2 * AKV_AR) * 2 + so, g_Vh + vbase + (size_t)r * SEQ + c0 + d);
            cp16(skv + (uint32_t)(3 * AKV_AR) * 2 + so, g_Vl + vbase + (size_t)r * SEQ + c0 + d);
        }
        cp_commit();
    };

    issue_kv(0, 0);

    float acc_o[8][4];
#pragma unroll
    for (int j = 0; j < 8; j++)
#pragma unroll
        for (int q = 0; q < 4; q++) acc_o[j][q] = 0.0f;
    float mi[2] = {-1e30f, -1e30f}, li[2] = {0.0f, 0.0f};

    const int a_row = lane & 15;
    const int a_kof = (lane >> 4) << 3;
    const int b_rof = ((lane >> 4) << 3) + (lane & 7);
    const int b_kof = ((lane >> 3) & 1) << 3;

    const int NC = SEQ / 64;   // 32
    for (int c = 0; c < NC; ++c) {
        const int st = c & 1;
        cp_wait0();
        __syncthreads();
        if (c + 1 < NC) issue_kv(c + 1, st ^ 1);

        const uint32_t skv = sbase + (uint32_t)(A_KV0 + st * AKV_ST) * 2;
        const uint32_t uKh = skv;
        const uint32_t uKl = skv + (uint32_t)AKV_AR * 2;
        const uint32_t uVh = skv + (uint32_t)(2 * AKV_AR) * 2;
        const uint32_t uVl = skv + (uint32_t)(3 * AKV_AR) * 2;

        // --- S = Q K^T (log2-scaled: Q pre-multiplied by 0.125*log2e) ---
        float acc_s[8][4];
#pragma unroll
        for (int j = 0; j < 8; j++)
#pragma unroll
            for (int q = 0; q < 4; q++) acc_s[j][q] = 0.0f;

#pragma unroll
        for (int ks = 0; ks < 4; ++ks) {
            uint32_t ah[4], al[4];
            {
                const uint32_t off = (uint32_t)(((q0 + a_row) * ASTR + ks * 16 + a_kof) * 2);
                ldsm4(ah[0], ah[1], ah[2], ah[3], uQh + off);
                ldsm4(al[0], al[1], al[2], al[3], uQl + off);
            }
#pragma unroll
            for (int p = 0; p < 4; ++p) {
                uint32_t bh_[4], bl_[4];
                const uint32_t off = (uint32_t)(((p * 16 + b_rof) * ASTR + ks * 16 + b_kof) * 2);
                ldsm4(bh_[0], bh_[1], bh_[2], bh_[3], uKh + off);
                ldsm4(bl_[0], bl_[1], bl_[2], bl_[3], uKl + off);
#pragma unroll
                for (int q = 0; q < 2; ++q) {
                    float* d = acc_s[p * 2 + q];
                    mma16816(d, ah, &bh_[q * 2]);
                    mma16816(d, ah, &bl_[q * 2]);
                    mma16816(d, al, &bh_[q * 2]);
                }
            }
        }

        // --- online softmax in exp2 domain; P stays in registers ---
#pragma unroll
        for (int half = 0; half < 2; ++half) {
            float rmax = -1e30f;
#pragma unroll
            for (int nj = 0; nj < 8; ++nj)
#pragma unroll
                for (int t = 0; t < 2; ++t)
                    rmax = fmaxf(rmax, acc_s[nj][half * 2 + t]);
            rmax = fmaxf(rmax, __shfl_xor_sync(0xffffffffu, rmax, 1));
            rmax = fmaxf(rmax, __shfl_xor_sync(0xffffffffu, rmax, 2));
            const float mn = fmaxf(mi[half], rmax);
            float rsum = 0.0f;
#pragma unroll
            for (int nj = 0; nj < 8; ++nj)
#pragma unroll
                for (int t = 0; t < 2; ++t) {
                    const float e = exp2f(acc_s[nj][half * 2 + t] - mn);
                    acc_s[nj][half * 2 + t] = e;
                    rsum += e;
                }
            rsum += __shfl_xor_sync(0xffffffffu, rsum, 1);
            rsum += __shfl_xor_sync(0xffffffffu, rsum, 2);
            const float alpha = exp2f(mi[half] - mn);
            li[half] = li[half] * alpha + rsum;
            mi[half] = mn;
#pragma unroll
            for (int nj = 0; nj < 8; ++nj)
#pragma unroll
                for (int t = 0; t < 2; ++t) acc_o[nj][half * 2 + t] *= alpha;
        }

        // --- O += P V, P fragments built in registers from acc_s ---
#pragma unroll
        for (int ks = 0; ks < 4; ++ks) {
            uint32_t ph[4], pl[4];
            split_pack(acc_s[2 * ks][0],     acc_s[2 * ks][1],     ph[0], pl[0]);
            split_pack(acc_s[2 * ks][2],     acc_s[2 * ks][3],     ph[1], pl[1]);
            split_pack(acc_s[2 * ks + 1][0], acc_s[2 * ks + 1][1], ph[2], pl[2]);
            split_pack(acc_s[2 * ks + 1][2], acc_s[2 * ks + 1][3], ph[3], pl[3]);
#pragma unroll
            for (int p = 0; p < 4; ++p) {
                uint32_t vh_[4], vl_[4];
                const uint32_t off = (uint32_t)(((p * 16 + b_rof) * ASTR + ks * 16 + b_kof) * 2);
                ldsm4(vh_[0], vh_[1], vh_[2], vh_[3], uVh + off);
                ldsm4(vl_[0], vl_[1], vl_[2], vl_[3], uVl + off);
#pragma unroll
                for (int q = 0; q < 2; ++q) {
                    float* d = acc_o[p * 2 + q];
                    mma16816(d, ph, &vh_[q * 2]);
                    mma16816(d, ph, &vl_[q * 2]);
                    mma16816(d, pl, &vh_[q * 2]);
                }
            }
        }
    }

    // Epilogue
    const int b_ = bh >> 4, h = bh & 15;
#pragma unroll
    for (int half = 0; half < 2; ++half) {
        const float inv = 1.0f / li[half];
        const int row = rblk * 128 + q0 + (lane >> 2) + half * 8;
        const size_t mrow = ((size_t)b_ * SEQ + row) * DIM + h * HD;
#pragma unroll
        for (int nj = 0; nj < 8; ++nj) {
            const float o0 = acc_o[nj][half * 2 + 0] * inv;
            const float o1 = acc_o[nj][half * 2 + 1] * inv;
            __nv_bfloat16 h0, l0, h1, l1;
            split2(o0, h0, l0); split2(o1, h1, l1);
            const int cc = nj * 8 + (lane & 3) * 2;
            *(__nv_bfloat162*)(g_oh + mrow + cc) = {h0, h1};
            *(__nv_bfloat162*)(g_ol + mrow + cc) = {l0, l1};
        }
    }
}

// ---------------------------------------------------------------------------

extern "C" void kernel_launch(void* const* d_in, const int* in_sizes, int n_in,
                              void* d_out, int out_size) {
    (void)in_sizes; (void)n_in; (void)out_size;
    const float* x  = (const float*)d_in[0];
    const float* Wq = (const float*)d_in[1];
    const float* Wk = (const float*)d_in[2];
    const float* Wv = (const float*)d_in[3];
    const float* Wo = (const float*)d_in[4];
    const float* bo = (const float*)d_in[5];
    float* out = (float*)d_out;

    cudaFuncSetAttribute(gemm_mma<0>, cudaFuncAttributeMaxDynamicSharedMemorySize, GSM_BYTES);
    cudaFuncSetAttribute(gemm_mma<1>, cudaFuncAttributeMaxDynamicSharedMemorySize, GSM_BYTES);
    cudaFuncSetAttribute(attn_mma,    cudaFuncAttributeMaxDynamicSharedMemorySize, A_TOTAL);

    __nv_bfloat16 *wh, *wl, *woh, *wol, *xh, *xl, *oh, *ol;
    cudaGetSymbolAddress((void**)&wh,  g_wh);
    cudaGetSymbolAddress((void**)&wl,  g_wl);
    cudaGetSymbolAddress((void**)&woh, g_woh);
    cudaGetSymbolAddress((void**)&wol, g_wol);
    cudaGetSymbolAddress((void**)&xh,  g_xh);
    cudaGetSymbolAddress((void**)&xl,  g_xl);
    cudaGetSymbolAddress((void**)&oh,  g_oh);
    cudaGetSymbolAddress((void**)&ol,  g_ol);

    split_x_kernel<<<MROWS * DIM / 1024, 256>>>(x);
    transpose_split4<<<dim3(32, 32, 4), dim3(32, 8)>>>(Wq, Wk, Wv, Wo);

    gemm_mma<0><<<dim3(24, 64), 256, GSM_BYTES>>>(xh, xl, wh, wl, nullptr, nullptr);
    attn_mma<<<dim3(16, 64), 256, A_TOTAL>>>();
    gemm_mma<1><<<dim3(8, 64), 256, GSM_BYTES>>>(oh, ol, woh, wol, out, bo);
}

// round 9
// speedup vs baseline: 1.2283x; 1.1908x over previous
#include <cuda_runtime.h>
#include <cuda_bf16.h>
#include <cuda_fp16.h>
#include <cstdint>

#define DIM    1024
#define HEADS  16
#define HD     64
#define BATCH  4
#define SEQ    2048
#define MROWS  (BATCH * SEQ)            // 8192
#define QKV_ELEMS (BATCH * HEADS * SEQ * HD)  // 8388608

// 0.125 * log2(e): folded into Q so softmax is pure exp2
#define SCALE_Q 0.18033688011112042f

// ---------------------------------------------------------------------------
// Scratch (allocation-free rule: __device__ globals)
// ---------------------------------------------------------------------------
// fp16 attention operands
__device__ __half g_Qhh[QKV_ELEMS], g_Qlh[QKV_ELEMS];  // [b,h,n,d], pre-scaled, hi/lo
__device__ __half g_Kf[QKV_ELEMS];                     // [b,h,n,d], single fp16
__device__ __half g_Vf[QKV_ELEMS];                     // [b,h,d,n], single fp16 (transposed)
// bf16 split operands for the GEMMs
__device__ __nv_bfloat16 g_xh[MROWS * DIM], g_xl[MROWS * DIM];
__device__ __nv_bfloat16 g_wh[3 * DIM * DIM], g_wl[3 * DIM * DIM];  // W^T [n][k]
__device__ __nv_bfloat16 g_woh[DIM * DIM], g_wol[DIM * DIM];        // Wo^T [n][k]
__device__ __nv_bfloat16 g_oh[MROWS * DIM], g_ol[MROWS * DIM];      // attn out [m][h*64+d]

// ---------------------------------------------------------------------------
// helpers
// ---------------------------------------------------------------------------
__device__ __forceinline__ uint32_t smem_u32(const void* p) {
    uint32_t a;
    asm("{ .reg .u64 t; cvta.to.shared.u64 t, %1; cvt.u32.u64 %0, t; }" : "=r"(a) : "l"(p));
    return a;
}
__device__ __forceinline__ void ldsm4(uint32_t& r0, uint32_t& r1, uint32_t& r2, uint32_t& r3,
                                      uint32_t addr) {
    asm volatile("ldmatrix.sync.aligned.m8n8.x4.shared.b16 {%0,%1,%2,%3}, [%4];"
                 : "=r"(r0), "=r"(r1), "=r"(r2), "=r"(r3) : "r"(addr));
}
// bf16 mma (GEMMs)
__device__ __forceinline__ void mma16816(float* d, const uint32_t* a, const uint32_t* b) {
    asm volatile(
        "mma.sync.aligned.m16n8k16.row.col.f32.bf16.bf16.f32 "
        "{%0,%1,%2,%3}, {%4,%5,%6,%7}, {%8,%9}, {%0,%1,%2,%3};"
        : "+f"(d[0]), "+f"(d[1]), "+f"(d[2]), "+f"(d[3])
        : "r"(a[0]), "r"(a[1]), "r"(a[2]), "r"(a[3]), "r"(b[0]), "r"(b[1]));
}
// fp16 mma (attention)
__device__ __forceinline__ void mma16816h(float* d, const uint32_t* a, const uint32_t* b) {
    asm volatile(
        "mma.sync.aligned.m16n8k16.row.col.f32.f16.f16.f32 "
        "{%0,%1,%2,%3}, {%4,%5,%6,%7}, {%8,%9}, {%0,%1,%2,%3};"
        : "+f"(d[0]), "+f"(d[1]), "+f"(d[2]), "+f"(d[3])
        : "r"(a[0]), "r"(a[1]), "r"(a[2]), "r"(a[3]), "r"(b[0]), "r"(b[1]));
}
__device__ __forceinline__ void cp16(uint32_t saddr, const void* gptr) {
    asm volatile("cp.async.cg.shared.global [%0], [%1], 16;" :: "r"(saddr), "l"(gptr));
}
__device__ __forceinline__ void cp_commit() {
    asm volatile("cp.async.commit_group;" ::: "memory");
}
__device__ __forceinline__ void cp_wait0() {
    asm volatile("cp.async.wait_group 0;" ::: "memory");
}
__device__ __forceinline__ float ex2(float x) {
    float y;
    asm("ex2.approx.ftz.f32 %0, %1;" : "=f"(y) : "f"(x));
    return y;
}
__device__ __forceinline__ void split2(float v, __nv_bfloat16& h, __nv_bfloat16& l) {
    h = __float2bfloat16(v);
    l = __float2bfloat16(v - __bfloat162float(h));
}
__device__ __forceinline__ void split2h(float v, __half& h, __half& l) {
    h = __float2half_rn(v);
    l = __float2half_rn(v - __half2float(h));
}
__device__ __forceinline__ void split_pack_h(float v0, float v1, uint32_t& ph, uint32_t& pl) {
    __half h0, l0, h1, l1;
    split2h(v0, h0, l0); split2h(v1, h1, l1);
    __half2 th = {h0, h1}, tl = {l0, l1};
    ph = *(uint32_t*)&th;
    pl = *(uint32_t*)&tl;
}

// ---------------------------------------------------------------------------
// Prep kernels
// ---------------------------------------------------------------------------
__global__ __launch_bounds__(256) void split_x_kernel(const float* __restrict__ x) {
    int i = (blockIdx.x * 256 + threadIdx.x) * 4;
    float4 v = *(const float4*)(x + i);
    __nv_bfloat16 h0, h1, h2, h3, l0, l1, l2, l3;
    split2(v.x, h0, l0); split2(v.y, h1, l1); split2(v.z, h2, l2); split2(v.w, h3, l3);
    *(__nv_bfloat162*)(g_xh + i)     = {h0, h1};
    *(__nv_bfloat162*)(g_xh + i + 2) = {h2, h3};
    *(__nv_bfloat162*)(g_xl + i)     = {l0, l1};
    *(__nv_bfloat162*)(g_xl + i + 2) = {l2, l3};
}

__global__ __launch_bounds__(256) void transpose_split4(const float* __restrict__ W0,
                                                        const float* __restrict__ W1,
                                                        const float* __restrict__ W2,
                                                        const float* __restrict__ W3) {
    __shared__ float t[32][33];
    const int z = blockIdx.z;
    const float* src = (z == 0) ? W0 : (z == 1) ? W1 : (z == 2) ? W2 : W3;
    __nv_bfloat16* dh = (z < 3) ? (g_wh + (size_t)z * DIM * DIM) : g_woh;
    __nv_bfloat16* dl = (z < 3) ? (g_wl + (size_t)z * DIM * DIM) : g_wol;

    const int bx = blockIdx.x * 32;
    const int by = blockIdx.y * 32;
    const int x = threadIdx.x, y0 = threadIdx.y;
#pragma unroll
    for (int i = 0; i < 32; i += 8)
        t[y0 + i][x] = src[(by + y0 + i) * DIM + bx + x];
    __syncthreads();
#pragma unroll
    for (int i = 0; i < 32; i += 8) {
        float v = t[x][y0 + i];
        __nv_bfloat16 h, l; split2(v, h, l);
        int o = (bx + y0 + i) * DIM + by + x;
        dh[o] = h; dl[o] = l;
    }
}

// ---------------------------------------------------------------------------
// bf16x3 split GEMM, cp.async 2-stage pipeline, BK=32, 2 CTAs/SM.
// MODE 0: QKV -> fp16 Q hi/lo (pre-scaled), fp16 K, fp16 V^T
// MODE 1: out proj + bias -> d_out (fp32). RB row-tiles per CTA (wave shaping).
// ---------------------------------------------------------------------------
#define GBK    32
#define GSTR   40
#define GARR   (128 * GSTR)
#define GSTAGE (4 * GARR)
#define GSM_BYTES (2 * GSTAGE * 2)     // 81920

template <int MODE, int RB>
__global__ __launch_bounds__(256, 2) void gemm_mma(
    const __nv_bfloat16* __restrict__ Ah, const __nv_bfloat16* __restrict__ Al,
    const __nv_bfloat16* __restrict__ Bh, const __nv_bfloat16* __restrict__ Bl,
    float* __restrict__ outp, const float* __restrict__ bo) {
    extern __shared__ __nv_bfloat16 sm[];

    const int tid  = threadIdx.x;
    const int lane = tid & 31;
    const int wid  = tid >> 5;
    const int wm   = wid & 1;
    const int wn   = wid >> 1;
    const int col0 = blockIdx.x * 128;

    const uint32_t sbase = smem_u32(sm);

    const int a_row = (lane & 15);
    const int a_kof = (lane >> 4) << 3;
    const int b_rof = ((lane >> 4) << 3) + (lane & 7);
    const int b_kof = ((lane >> 3) & 1) << 3;

    const __nv_bfloat16* pBh = Bh + (size_t)col0 * DIM;
    const __nv_bfloat16* pBl = Bl + (size_t)col0 * DIM;

    for (int rb = 0; rb < RB; ++rb) {
        const int row0 = (blockIdx.y * RB + rb) * 128;
        const __nv_bfloat16* pAh = Ah + (size_t)row0 * DIM;
        const __nv_bfloat16* pAl = Al + (size_t)row0 * DIM;

        float acc[4][4][4];
#pragma unroll
        for (int i = 0; i < 4; i++)
#pragma unroll
            for (int j = 0; j < 4; j++)
#pragma unroll
                for (int q = 0; q < 4; q++) acc[i][j][q] = 0.0f;

        auto issue = [&](int c, int st) {
            const int k0 = c * GBK;
            const uint32_t sst = sbase + (uint32_t)(st * GSTAGE) * 2;
#pragma unroll
            for (int it = 0; it < 2; ++it) {
                const int lin = it * 256 + tid;   // 0..511 : 128 rows x 4 groups
                const int rr = lin >> 2;
                const int cg = (lin & 3) * 8;
                const uint32_t so = (uint32_t)(rr * GSTR + cg) * 2;
                const size_t go = (size_t)rr * DIM + k0 + cg;
                cp16(sst + so,                            pAh + go);
                cp16(sst + (uint32_t)GARR * 2 + so,       pAl + go);
                cp16(sst + (uint32_t)(2 * GARR) * 2 + so, pBh + go);
                cp16(sst + (uint32_t)(3 * GARR) * 2 + so, pBl + go);
            }
            cp_commit();
        };

        issue(0, 0);

        const int NC = DIM / GBK;   // 32
        for (int c = 0; c < NC; ++c) {
            const int st = c & 1;
            cp_wait0();
            __syncthreads();
            if (c + 1 < NC) issue(c + 1, st ^ 1);

            const uint32_t sA = sbase + (uint32_t)(st * GSTAGE) * 2;
            const uint32_t sAh = sA;
            const uint32_t sAl = sA + (uint32_t)GARR * 2;
            const uint32_t sBh = sA + (uint32_t)(2 * GARR) * 2;
            const uint32_t sBl = sA + (uint32_t)(3 * GARR) * 2;

#pragma unroll
            for (int ks = 0; ks < GBK / 16; ++ks) {
                uint32_t bh[2][4], bl[2][4];
#pragma unroll
                for (int p = 0; p < 2; ++p) {
                    const uint32_t off =
                        (uint32_t)(((wn * 32 + p * 16 + b_rof) * GSTR + ks * 16 + b_kof) * 2);
                    ldsm4(bh[p][0], bh[p][1], bh[p][2], bh[p][3], sBh + off);
                    ldsm4(bl[p][0], bl[p][1], bl[p][2], bl[p][3], sBl + off);
                }
#pragma unroll
                for (int mi = 0; mi < 4; ++mi) {
                    uint32_t ah[4], al[4];
                    const uint32_t off =
                        (uint32_t)(((wm * 64 + mi * 16 + a_row) * GSTR + ks * 16 + a_kof) * 2);
                    ldsm4(ah[0], ah[1], ah[2], ah[3], sAh + off);
                    ldsm4(al[0], al[1], al[2], al[3], sAl + off);
#pragma unroll
                    for (int p = 0; p < 2; ++p)
#pragma unroll
                        for (int q = 0; q < 2; ++q) {
                            float* d = acc[mi][p * 2 + q];
                            mma16816(d, ah, &bh[p][q * 2]);
                            mma16816(d, ah, &bl[p][q * 2]);
                            mma16816(d, al, &bh[p][q * 2]);
                        }
                }
            }
        }

#pragma unroll
        for (int mi = 0; mi < 4; ++mi) {
#pragma unroll
            for (int nj = 0; nj < 4; ++nj) {
                const int r = row0 + wm * 64 + mi * 16 + (lane >> 2);
                const int cgl = col0 + wn * 32 + nj * 8 + (lane & 3) * 2;
#pragma unroll
                for (int half = 0; half < 2; ++half) {
                    const int rr = r + half * 8;
                    float v0 = acc[mi][nj][half * 2 + 0];
                    float v1 = acc[mi][nj][half * 2 + 1];
                    if (MODE == 0) {
                        const int b_ = rr >> 11, n = rr & 2047;
                        const int wsel = cgl >> 10;
                        const int c1 = cgl & 1023;
                        const int h = c1 >> 6, d0 = c1 & 63;
                        if (wsel == 0) {
                            v0 *= SCALE_Q; v1 *= SCALE_Q;
                            __half h0, l0, h1, l1;
                            split2h(v0, h0, l0); split2h(v1, h1, l1);
                            const size_t o = ((size_t)(b_ * HEADS + h) * SEQ + n) * HD + d0;
                            *(__half2*)(g_Qhh + o) = {h0, h1};
                            *(__half2*)(g_Qlh + o) = {l0, l1};
                        } else if (wsel == 1) {
                            const size_t o = ((size_t)(b_ * HEADS + h) * SEQ + n) * HD + d0;
                            *(__half2*)(g_Kf + o) = {__float2half_rn(v0), __float2half_rn(v1)};
                        } else {
                            const size_t o = ((size_t)(b_ * HEADS + h) * HD + d0) * SEQ + n;
                            g_Vf[o]       = __float2half_rn(v0);
                            g_Vf[o + SEQ] = __float2half_rn(v1);
                        }
                    } else {
                        *(float2*)(outp + (size_t)rr * DIM + cgl) =
                            make_float2(v0 + bo[cgl], v1 + bo[cgl + 1]);
                    }
                }
            }
        }
        if (rb + 1 < RB) __syncthreads();
    }
}

// ---------------------------------------------------------------------------
// Flash attention, fp16 2-product: S = Qh·K + Ql·K, O += Ph·V + Pl·V.
// 256 thr, 8 warps x 16 q-rows, KV chunk 64, cp.async 2-stage, 2 CTAs/SM.
// Q pre-scaled by 0.125*log2e; softmax in exp2 domain; P in registers.
// ---------------------------------------------------------------------------
#define ASTR   72
#define AQ_ELE (128 * ASTR)            // 9216 per Q array (halves)
#define KV_AR  (64 * ASTR)             // 4608 per K / V array
#define AST_EL (2 * KV_AR)             // 9216 per stage (K + V)
#define A_KV0  (2 * AQ_ELE)            // 18432
#define A_TOTAL ((A_KV0 + 2 * AST_EL) * 2)   // 73728 bytes

__global__ __launch_bounds__(256, 2) void attn_mma() {
    extern __shared__ __half sma[];

    const int bh   = blockIdx.y;
    const int rblk = blockIdx.x;
    const int tid  = threadIdx.x;
    const int lane = tid & 31;
    const int wid  = tid >> 5;
    const int q0   = wid * 16;

    const size_t qbase = ((size_t)bh * SEQ + rblk * 128) * HD;
    const size_t kbase = (size_t)bh * SEQ * HD;
    const size_t vbase = (size_t)bh * HD * SEQ;

    const uint32_t sbase = smem_u32(sma);
    const uint32_t uQh = sbase;
    const uint32_t uQl = sbase + (uint32_t)AQ_ELE * 2;

    // Q tile 128x64 hi/lo via cp.async
#pragma unroll
    for (int it = 0; it < 4; ++it) {
        const int lin = it * 256 + tid;
        const int r = lin >> 3, d = (lin & 7) * 8;
        const uint32_t so = (uint32_t)(r * ASTR + d) * 2;
        cp16(uQh + so, g_Qhh + qbase + (size_t)r * HD + d);
        cp16(uQl + so, g_Qlh + qbase + (size_t)r * HD + d);
    }
    cp_commit();

    auto issue_kv = [&](int chunk, int st) {
        const int c0 = chunk * 64;
        const uint32_t skv = sbase + (uint32_t)(A_KV0 + st * AST_EL) * 2;
#pragma unroll
        for (int it = 0; it < 2; ++it) {
            const int lin = it * 256 + tid;
            const int r = lin >> 3, d = (lin & 7) * 8;
            const uint32_t so = (uint32_t)(r * ASTR + d) * 2;
            cp16(skv + so,                        g_Kf + kbase + (size_t)(c0 + r) * HD + d);
            cp16(skv + (uint32_t)KV_AR * 2 + so,  g_Vf + vbase + (size_t)r * SEQ + c0 + d);
        }
        cp_commit();
    };

    issue_kv(0, 0);

    float acc_o[8][4];
#pragma unroll
    for (int j = 0; j < 8; j++)
#pragma unroll
        for (int q = 0; q < 4; q++) acc_o[j][q] = 0.0f;
    float mi[2] = {-1e30f, -1e30f}, li[2] = {0.0f, 0.0f};

    const int a_row = lane & 15;
    const int a_kof = (lane >> 4) << 3;
    const int b_rof = ((lane >> 4) << 3) + (lane & 7);
    const int b_kof = ((lane >> 3) & 1) << 3;

    const int NC = SEQ / 64;   // 32
    for (int c = 0; c < NC; ++c) {
        const int st = c & 1;
        cp_wait0();
        __syncthreads();
        if (c + 1 < NC) issue_kv(c + 1, st ^ 1);

        const uint32_t skv = sbase + (uint32_t)(A_KV0 + st * AST_EL) * 2;
        const uint32_t uK = skv;
        const uint32_t uV = skv + (uint32_t)KV_AR * 2;

        // --- S = Qh K + Ql K ---
        float acc_s[8][4];
#pragma unroll
        for (int j = 0; j < 8; j++)
#pragma unroll
            for (int q = 0; q < 4; q++) acc_s[j][q] = 0.0f;

#pragma unroll
        for (int ks = 0; ks < 4; ++ks) {
            uint32_t ah[4], al[4];
            {
                const uint32_t off = (uint32_t)(((q0 + a_row) * ASTR + ks * 16 + a_kof) * 2);
                ldsm4(ah[0], ah[1], ah[2], ah[3], uQh + off);
                ldsm4(al[0], al[1], al[2], al[3], uQl + off);
            }
#pragma unroll
            for (int p = 0; p < 4; ++p) {
                uint32_t kh_[4];
                const uint32_t off = (uint32_t)(((p * 16 + b_rof) * ASTR + ks * 16 + b_kof) * 2);
                ldsm4(kh_[0], kh_[1], kh_[2], kh_[3], uK + off);
#pragma unroll
                for (int q = 0; q < 2; ++q) {
                    float* d = acc_s[p * 2 + q];
                    mma16816h(d, ah, &kh_[q * 2]);
                    mma16816h(d, al, &kh_[q * 2]);
                }
            }
        }

        // --- online softmax in exp2 domain ---
#pragma unroll
        for (int half = 0; half < 2; ++half) {
            float rmax = -1e30f;
#pragma unroll
            for (int nj = 0; nj < 8; ++nj)
#pragma unroll
                for (int t = 0; t < 2; ++t)
                    rmax = fmaxf(rmax, acc_s[nj][half * 2 + t]);
            rmax = fmaxf(rmax, __shfl_xor_sync(0xffffffffu, rmax, 1));
            rmax = fmaxf(rmax, __shfl_xor_sync(0xffffffffu, rmax, 2));
            const float mn = fmaxf(mi[half], rmax);
            float rsum = 0.0f;
#pragma unroll
            for (int nj = 0; nj < 8; ++nj)
#pragma unroll
                for (int t = 0; t < 2; ++t) {
                    const float e = ex2(acc_s[nj][half * 2 + t] - mn);
                    acc_s[nj][half * 2 + t] = e;
                    rsum += e;
                }
            rsum += __shfl_xor_sync(0xffffffffu, rsum, 1);
            rsum += __shfl_xor_sync(0xffffffffu, rsum, 2);
            const float alpha = ex2(mi[half] - mn);
            li[half] = li[half] * alpha + rsum;
            mi[half] = mn;
#pragma unroll
            for (int nj = 0; nj < 8; ++nj)
#pragma unroll
                for (int t = 0; t < 2; ++t) acc_o[nj][half * 2 + t] *= alpha;
        }

        // --- O += Ph V + Pl V ---
#pragma unroll
        for (int ks = 0; ks < 4; ++ks) {
            uint32_t ph[4], pl[4];
            split_pack_h(acc_s[2 * ks][0],     acc_s[2 * ks][1],     ph[0], pl[0]);
            split_pack_h(acc_s[2 * ks][2],     acc_s[2 * ks][3],     ph[1], pl[1]);
            split_pack_h(acc_s[2 * ks + 1][0], acc_s[2 * ks + 1][1], ph[2], pl[2]);
            split_pack_h(acc_s[2 * ks + 1][2], acc_s[2 * ks + 1][3], ph[3], pl[3]);
#pragma unroll
            for (int p = 0; p < 4; ++p) {
                uint32_t vh_[4];
                const uint32_t off = (uint32_t)(((p * 16 + b_rof) * ASTR + ks * 16 + b_kof) * 2);
                ldsm4(vh_[0], vh_[1], vh_[2], vh_[3], uV + off);
#pragma unroll
                for (int q = 0; q < 2; ++q) {
                    float* d = acc_o[p * 2 + q];
                    mma16816h(d, ph, &vh_[q * 2]);
                    mma16816h(d, pl, &vh_[q * 2]);
                }
            }
        }
    }

    // Epilogue: normalize, split bf16 hi/lo for proj GEMM
    const int b_ = bh >> 4, h = bh & 15;
#pragma unroll
    for (int half = 0; half < 2; ++half) {
        const float inv = 1.0f / li[half];
        const int row = rblk * 128 + q0 + (lane >> 2) + half * 8;
        const size_t mrow = ((size_t)b_ * SEQ + row) * DIM + h * HD;
#pragma unroll
        for (int nj = 0; nj < 8; ++nj) {
            const float o0 = acc_o[nj][half * 2 + 0] * inv;
            const float o1 = acc_o[nj][half * 2 + 1] * inv;
            __nv_bfloat16 h0, l0, h1, l1;
            split2(o0, h0, l0); split2(o1, h1, l1);
            const int cc = nj * 8 + (lane & 3) * 2;
            *(__nv_bfloat162*)(g_oh + mrow + cc) = {h0, h1};
            *(__nv_bfloat162*)(g_ol + mrow + cc) = {l0, l1};
        }
    }
}

// ---------------------------------------------------------------------------

extern "C" void kernel_launch(void* const* d_in, const int* in_sizes, int n_in,
                              void* d_out, int out_size) {
    (void)in_sizes; (void)n_in; (void)out_size;
    const float* x  = (const float*)d_in[0];
    const float* Wq = (const float*)d_in[1];
    const float* Wk = (const float*)d_in[2];
    const float* Wv = (const float*)d_in[3];
    const float* Wo = (const float*)d_in[4];
    const float* bo = (const float*)d_in[5];
    float* out = (float*)d_out;

    cudaFuncSetAttribute((const void*)gemm_mma<0, 1>,
                         cudaFuncAttributeMaxDynamicSharedMemorySize, GSM_BYTES);
    cudaFuncSetAttribute((const void*)gemm_mma<1, 2>,
                         cudaFuncAttributeMaxDynamicSharedMemorySize, GSM_BYTES);
    cudaFuncSetAttribute((const void*)attn_mma,
                         cudaFuncAttributeMaxDynamicSharedMemorySize, A_TOTAL);

    __nv_bfloat16 *wh, *wl, *woh, *wol, *xh, *xl, *oh, *ol;
    cudaGetSymbolAddress((void**)&wh,  g_wh);
    cudaGetSymbolAddress((void**)&wl,  g_wl);
    cudaGetSymbolAddress((void**)&woh, g_woh);
    cudaGetSymbolAddress((void**)&wol, g_wol);
    cudaGetSymbolAddress((void**)&xh,  g_xh);
    cudaGetSymbolAddress((void**)&xl,  g_xl);
    cudaGetSymbolAddress((void**)&oh,  g_oh);
    cudaGetSymbolAddress((void**)&ol,  g_ol);

    split_x_kernel<<<MROWS * DIM / 1024, 256>>>(x);
    transpose_split4<<<dim3(32, 32, 4), dim3(32, 8)>>>(Wq, Wk, Wv, Wo);

    gemm_mma<0, 1><<<dim3(24, 64), 256, GSM_BYTES>>>(xh, xl, wh, wl, nullptr, nullptr);
    attn_mma<<<dim3(16, 64), 256, A_TOTAL>>>();
    gemm_mma<1, 2><<<dim3(8, 32), 256, GSM_BYTES>>>(oh, ol, woh, wol, out, bo);
}

// round 10
// speedup vs baseline: 1.4183x; 1.1547x over previous
#include <cuda_runtime.h>
#include <cuda_bf16.h>
#include <cuda_fp16.h>
#include <cstdint>

#define DIM    1024
#define HEADS  16
#define HD     64
#define BATCH  4
#define SEQ    2048
#define MROWS  (BATCH * SEQ)            // 8192
#define QKV_ELEMS (BATCH * HEADS * SEQ * HD)  // 8388608

// 0.125 * log2(e): folded into Q so softmax is pure exp2
#define SCALE_Q 0.18033688011112042f

// ---------------------------------------------------------------------------
// Scratch (allocation-free rule: __device__ globals)
// ---------------------------------------------------------------------------
// fp16 attention operands
__device__ __half g_Qhh[QKV_ELEMS], g_Qlh[QKV_ELEMS];  // [b,h,n,d], pre-scaled, hi/lo
__device__ __half g_Kf[QKV_ELEMS];                     // [b,h,n,d], single fp16
__device__ __half g_Vf[QKV_ELEMS];                     // [b,h,d,n], single fp16 (transposed)
// fp16 operands for QKV GEMM
__device__ __half g_xfh[MROWS * DIM], g_xfl[MROWS * DIM];  // x hi/lo
__device__ __half g_wf[3 * DIM * DIM];                     // {Wq,Wk,Wv}^T [n][k] fp16
// bf16 split operands for the out-proj GEMM
__device__ __nv_bfloat16 g_woh[DIM * DIM], g_wol[DIM * DIM];   // Wo^T [n][k]
__device__ __nv_bfloat16 g_oh[MROWS * DIM], g_ol[MROWS * DIM]; // attn out [m][h*64+d]

// ---------------------------------------------------------------------------
// helpers
// ---------------------------------------------------------------------------
__device__ __forceinline__ uint32_t smem_u32(const void* p) {
    uint32_t a;
    asm("{ .reg .u64 t; cvta.to.shared.u64 t, %1; cvt.u32.u64 %0, t; }" : "=r"(a) : "l"(p));
    return a;
}
__device__ __forceinline__ void ldsm4(uint32_t& r0, uint32_t& r1, uint32_t& r2, uint32_t& r3,
                                      uint32_t addr) {
    asm volatile("ldmatrix.sync.aligned.m8n8.x4.shared.b16 {%0,%1,%2,%3}, [%4];"
                 : "=r"(r0), "=r"(r1), "=r"(r2), "=r"(r3) : "r"(addr));
}
// bf16 mma (out-proj GEMM)
__device__ __forceinline__ void mma16816(float* d, const uint32_t* a, const uint32_t* b) {
    asm volatile(
        "mma.sync.aligned.m16n8k16.row.col.f32.bf16.bf16.f32 "
        "{%0,%1,%2,%3}, {%4,%5,%6,%7}, {%8,%9}, {%0,%1,%2,%3};"
        : "+f"(d[0]), "+f"(d[1]), "+f"(d[2]), "+f"(d[3])
        : "r"(a[0]), "r"(a[1]), "r"(a[2]), "r"(a[3]), "r"(b[0]), "r"(b[1]));
}
// fp16 mma (QKV GEMM + attention)
__device__ __forceinline__ void mma16816h(float* d, const uint32_t* a, const uint32_t* b) {
    asm volatile(
        "mma.sync.aligned.m16n8k16.row.col.f32.f16.f16.f32 "
        "{%0,%1,%2,%3}, {%4,%5,%6,%7}, {%8,%9}, {%0,%1,%2,%3};"
        : "+f"(d[0]), "+f"(d[1]), "+f"(d[2]), "+f"(d[3])
        : "r"(a[0]), "r"(a[1]), "r"(a[2]), "r"(a[3]), "r"(b[0]), "r"(b[1]));
}
__device__ __forceinline__ void cp16(uint32_t saddr, const void* gptr) {
    asm volatile("cp.async.cg.shared.global [%0], [%1], 16;" :: "r"(saddr), "l"(gptr));
}
__device__ __forceinline__ void cp_commit() {
    asm volatile("cp.async.commit_group;" ::: "memory");
}
__device__ __forceinline__ void cp_wait0() {
    asm volatile("cp.async.wait_group 0;" ::: "memory");
}
__device__ __forceinline__ float ex2(float x) {
    float y;
    asm("ex2.approx.ftz.f32 %0, %1;" : "=f"(y) : "f"(x));
    return y;
}
__device__ __forceinline__ void split2(float v, __nv_bfloat16& h, __nv_bfloat16& l) {
    h = __float2bfloat16(v);
    l = __float2bfloat16(v - __bfloat162float(h));
}
__device__ __forceinline__ void split2h(float v, __half& h, __half& l) {
    h = __float2half_rn(v);
    l = __float2half_rn(v - __half2float(h));
}
__device__ __forceinline__ void split_pack_h(float v0, float v1, uint32_t& ph, uint32_t& pl) {
    __half h0, l0, h1, l1;
    split2h(v0, h0, l0); split2h(v1, h1, l1);
    __half2 th = {h0, h1}, tl = {l0, l1};
    ph = *(uint32_t*)&th;
    pl = *(uint32_t*)&tl;
}

// ---------------------------------------------------------------------------
// Prep kernels
// ---------------------------------------------------------------------------
__global__ __launch_bounds__(256) void split_x_kernel(const float* __restrict__ x) {
    int i = (blockIdx.x * 256 + threadIdx.x) * 4;
    float4 v = *(const float4*)(x + i);
    __half h0, h1, h2, h3, l0, l1, l2, l3;
    split2h(v.x, h0, l0); split2h(v.y, h1, l1); split2h(v.z, h2, l2); split2h(v.w, h3, l3);
    *(__half2*)(g_xfh + i)     = {h0, h1};
    *(__half2*)(g_xfh + i + 2) = {h2, h3};
    *(__half2*)(g_xfl + i)     = {l0, l1};
    *(__half2*)(g_xfl + i + 2) = {l2, l3};
}

// z<3: Wq/Wk/Wv -> g_wf fp16; z==3: Wo -> g_woh/g_wol bf16 hi/lo
__global__ __launch_bounds__(256) void transpose_split4(const float* __restrict__ W0,
                                                        const float* __restrict__ W1,
                                                        const float* __restrict__ W2,
                                                        const float* __restrict__ W3) {
    __shared__ float t[32][33];
    const int z = blockIdx.z;
    const float* src = (z == 0) ? W0 : (z == 1) ? W1 : (z == 2) ? W2 : W3;

    const int bx = blockIdx.x * 32;
    const int by = blockIdx.y * 32;
    const int x = threadIdx.x, y0 = threadIdx.y;
#pragma unroll
    for (int i = 0; i < 32; i += 8)
        t[y0 + i][x] = src[(by + y0 + i) * DIM + bx + x];
    __syncthreads();
#pragma unroll
    for (int i = 0; i < 32; i += 8) {
        float v = t[x][y0 + i];
        int o = (bx + y0 + i) * DIM + by + x;
        if (z < 3) {
            g_wf[(size_t)z * DIM * DIM + o] = __float2half_rn(v);
        } else {
            __nv_bfloat16 h, l; split2(v, h, l);
            g_woh[o] = h; g_wol[o] = l;
        }
    }
}

// ---------------------------------------------------------------------------
// QKV GEMM: fp16 2-product (xh·W + xl·W), cp.async 2-stage, BK=32, 2 CTAs/SM.
// Epilogue -> fp16 Q hi/lo (pre-scaled), fp16 K, fp16 V^T.
// ---------------------------------------------------------------------------
#define GBK    32
#define GSTR   40
#define GARR   (128 * GSTR)            // 5120 elems
#define G0STAGE (3 * GARR)             // 15360 elems
#define G0SM_BYTES (2 * G0STAGE * 2)   // 61440

__global__ __launch_bounds__(256, 2) void gemm_qkv(
    const __half* __restrict__ Ah, const __half* __restrict__ Al,
    const __half* __restrict__ B) {
    extern __shared__ __half smq[];

    const int tid  = threadIdx.x;
    const int lane = tid & 31;
    const int wid  = tid >> 5;
    const int wm   = wid & 1;
    const int wn   = wid >> 1;
    const int row0 = blockIdx.y * 128;
    const int col0 = blockIdx.x * 128;

    const __half* pAh = Ah + (size_t)row0 * DIM;
    const __half* pAl = Al + (size_t)row0 * DIM;
    const __half* pB  = B  + (size_t)col0 * DIM;

    const uint32_t sbase = smem_u32(smq);

    float acc[4][4][4];
#pragma unroll
    for (int i = 0; i < 4; i++)
#pragma unroll
        for (int j = 0; j < 4; j++)
#pragma unroll
            for (int q = 0; q < 4; q++) acc[i][j][q] = 0.0f;

    const int a_row = (lane & 15);
    const int a_kof = (lane >> 4) << 3;
    const int b_rof = ((lane >> 4) << 3) + (lane & 7);
    const int b_kof = ((lane >> 3) & 1) << 3;

    auto issue = [&](int c, int st) {
        const int k0 = c * GBK;
        const uint32_t sst = sbase + (uint32_t)(st * G0STAGE) * 2;
#pragma unroll
        for (int it = 0; it < 2; ++it) {
            const int lin = it * 256 + tid;   // 0..511 : 128 rows x 4 groups
            const int rr = lin >> 2;
            const int cg = (lin & 3) * 8;
            const uint32_t so = (uint32_t)(rr * GSTR + cg) * 2;
            const size_t go = (size_t)rr * DIM + k0 + cg;
            cp16(sst + so,                       pAh + go);
            cp16(sst + (uint32_t)GARR * 2 + so,  pAl + go);
            cp16(sst + (uint32_t)(2 * GARR) * 2 + so, pB + go);
        }
        cp_commit();
    };

    issue(0, 0);

    const int NC = DIM / GBK;   // 32
    for (int c = 0; c < NC; ++c) {
        const int st = c & 1;
        cp_wait0();
        __syncthreads();
        if (c + 1 < NC) issue(c + 1, st ^ 1);

        const uint32_t sA = sbase + (uint32_t)(st * G0STAGE) * 2;
        const uint32_t sAh = sA;
        const uint32_t sAl = sA + (uint32_t)GARR * 2;
        const uint32_t sB  = sA + (uint32_t)(2 * GARR) * 2;

#pragma unroll
        for (int ks = 0; ks < GBK / 16; ++ks) {
            uint32_t bf[2][4];
#pragma unroll
            for (int p = 0; p < 2; ++p) {
                const uint32_t off =
                    (uint32_t)(((wn * 32 + p * 16 + b_rof) * GSTR + ks * 16 + b_kof) * 2);
                ldsm4(bf[p][0], bf[p][1], bf[p][2], bf[p][3], sB + off);
            }
#pragma unroll
            for (int mi = 0; mi < 4; ++mi) {
                uint32_t ah[4], al[4];
                const uint32_t off =
                    (uint32_t)(((wm * 64 + mi * 16 + a_row) * GSTR + ks * 16 + a_kof) * 2);
                ldsm4(ah[0], ah[1], ah[2], ah[3], sAh + off);
                ldsm4(al[0], al[1], al[2], al[3], sAl + off);
#pragma unroll
                for (int p = 0; p < 2; ++p)
#pragma unroll
                    for (int q = 0; q < 2; ++q) {
                        float* d = acc[mi][p * 2 + q];
                        mma16816h(d, ah, &bf[p][q * 2]);
                        mma16816h(d, al, &bf[p][q * 2]);
                    }
            }
        }
    }

#pragma unroll
    for (int mi = 0; mi < 4; ++mi) {
#pragma unroll
        for (int nj = 0; nj < 4; ++nj) {
            const int r = row0 + wm * 64 + mi * 16 + (lane >> 2);
            const int cgl = col0 + wn * 32 + nj * 8 + (lane & 3) * 2;
#pragma unroll
            for (int half = 0; half < 2; ++half) {
                const int rr = r + half * 8;
                float v0 = acc[mi][nj][half * 2 + 0];
                float v1 = acc[mi][nj][half * 2 + 1];
                const int b_ = rr >> 11, n = rr & 2047;
                const int wsel = cgl >> 10;
                const int c1 = cgl & 1023;
                const int h = c1 >> 6, d0 = c1 & 63;
                if (wsel == 0) {
                    v0 *= SCALE_Q; v1 *= SCALE_Q;
                    __half h0, l0, h1, l1;
                    split2h(v0, h0, l0); split2h(v1, h1, l1);
                    const size_t o = ((size_t)(b_ * HEADS + h) * SEQ + n) * HD + d0;
                    *(__half2*)(g_Qhh + o) = {h0, h1};
                    *(__half2*)(g_Qlh + o) = {l0, l1};
                } else if (wsel == 1) {
                    const size_t o = ((size_t)(b_ * HEADS + h) * SEQ + n) * HD + d0;
                    *(__half2*)(g_Kf + o) = {__float2half_rn(v0), __float2half_rn(v1)};
                } else {
                    const size_t o = ((size_t)(b_ * HEADS + h) * HD + d0) * SEQ + n;
                    g_Vf[o]       = __float2half_rn(v0);
                    g_Vf[o + SEQ] = __float2half_rn(v1);
                }
            }
        }
    }
}

// ---------------------------------------------------------------------------
// Out-proj GEMM: bf16x3 split (precision reserve), cp.async 2-stage, BK=32,
// 2 CTAs/SM, RB=2 row-tiles per CTA (single wave).
// ---------------------------------------------------------------------------
#define GSTAGE (4 * GARR)
#define GSM_BYTES (2 * GSTAGE * 2)     // 81920

__global__ __launch_bounds__(256, 2) void gemm_out(
    const __nv_bfloat16* __restrict__ Ah, const __nv_bfloat16* __restrict__ Al,
    const __nv_bfloat16* __restrict__ Bh, const __nv_bfloat16* __restrict__ Bl,
    float* __restrict__ outp, const float* __restrict__ bo) {
    extern __shared__ __nv_bfloat16 smo[];

    const int tid  = threadIdx.x;
    const int lane = tid & 31;
    const int wid  = tid >> 5;
    const int wm   = wid & 1;
    const int wn   = wid >> 1;
    const int col0 = blockIdx.x * 128;

    const uint32_t sbase = smem_u32(smo);

    const int a_row = (lane & 15);
    const int a_kof = (lane >> 4) << 3;
    const int b_rof = ((lane >> 4) << 3) + (lane & 7);
    const int b_kof = ((lane >> 3) & 1) << 3;

    const __nv_bfloat16* pBh = Bh + (size_t)col0 * DIM;
    const __nv_bfloat16* pBl = Bl + (size_t)col0 * DIM;

    for (int rb = 0; rb < 2; ++rb) {
        const int row0 = (blockIdx.y * 2 + rb) * 128;
        const __nv_bfloat16* pAh = Ah + (size_t)row0 * DIM;
        const __nv_bfloat16* pAl = Al + (size_t)row0 * DIM;

        float acc[4][4][4];
#pragma unroll
        for (int i = 0; i < 4; i++)
#pragma unroll
            for (int j = 0; j < 4; j++)
#pragma unroll
                for (int q = 0; q < 4; q++) acc[i][j][q] = 0.0f;

        auto issue = [&](int c, int st) {
            const int k0 = c * GBK;
            const uint32_t sst = sbase + (uint32_t)(st * GSTAGE) * 2;
#pragma unroll
            for (int it = 0; it < 2; ++it) {
                const int lin = it * 256 + tid;
                const int rr = lin >> 2;
                const int cg = (lin & 3) * 8;
                const uint32_t so = (uint32_t)(rr * GSTR + cg) * 2;
                const size_t go = (size_t)rr * DIM + k0 + cg;
                cp16(sst + so,                            pAh + go);
                cp16(sst + (uint32_t)GARR * 2 + so,       pAl + go);
                cp16(sst + (uint32_t)(2 * GARR) * 2 + so, pBh + go);
                cp16(sst + (uint32_t)(3 * GARR) * 2 + so, pBl + go);
            }
            cp_commit();
        };

        issue(0, 0);

        const int NC = DIM / GBK;
        for (int c = 0; c < NC; ++c) {
            const int st = c & 1;
            cp_wait0();
            __syncthreads();
            if (c + 1 < NC) issue(c + 1, st ^ 1);

            const uint32_t sA = sbase + (uint32_t)(st * GSTAGE) * 2;
            const uint32_t sAh = sA;
            const uint32_t sAl = sA + (uint32_t)GARR * 2;
            const uint32_t sBh = sA + (uint32_t)(2 * GARR) * 2;
            const uint32_t sBl = sA + (uint32_t)(3 * GARR) * 2;

#pragma unroll
            for (int ks = 0; ks < GBK / 16; ++ks) {
                uint32_t bh[2][4], bl[2][4];
#pragma unroll
                for (int p = 0; p < 2; ++p) {
                    const uint32_t off =
                        (uint32_t)(((wn * 32 + p * 16 + b_rof) * GSTR + ks * 16 + b_kof) * 2);
                    ldsm4(bh[p][0], bh[p][1], bh[p][2], bh[p][3], sBh + off);
                    ldsm4(bl[p][0], bl[p][1], bl[p][2], bl[p][3], sBl + off);
                }
#pragma unroll
                for (int mi = 0; mi < 4; ++mi) {
                    uint32_t ah[4], al[4];
                    const uint32_t off =
                        (uint32_t)(((wm * 64 + mi * 16 + a_row) * GSTR + ks * 16 + a_kof) * 2);
                    ldsm4(ah[0], ah[1], ah[2], ah[3], sAh + off);
                    ldsm4(al[0], al[1], al[2], al[3], sAl + off);
#pragma unroll
                    for (int p = 0; p < 2; ++p)
#pragma unroll
                        for (int q = 0; q < 2; ++q) {
                            float* d = acc[mi][p * 2 + q];
                            mma16816(d, ah, &bh[p][q * 2]);
                            mma16816(d, ah, &bl[p][q * 2]);
                            mma16816(d, al, &bh[p][q * 2]);
                        }
                }
            }
        }

#pragma unroll
        for (int mi = 0; mi < 4; ++mi) {
#pragma unroll
            for (int nj = 0; nj < 4; ++nj) {
                const int r = row0 + wm * 64 + mi * 16 + (lane >> 2);
                const int cgl = col0 + wn * 32 + nj * 8 + (lane & 3) * 2;
#pragma unroll
                for (int half = 0; half < 2; ++half) {
                    const int rr = r + half * 8;
                    *(float2*)(outp + (size_t)rr * DIM + cgl) = make_float2(
                        acc[mi][nj][half * 2 + 0] + bo[cgl],
                        acc[mi][nj][half * 2 + 1] + bo[cgl + 1]);
                }
            }
        }
        if (rb == 0) __syncthreads();
    }
}

// ---------------------------------------------------------------------------
// Flash attention, fp16 2-product (unchanged from R9 passing version).
// ---------------------------------------------------------------------------
#define ASTR   72
#define AQ_ELE (128 * ASTR)            // 9216 per Q array (halves)
#define KV_AR  (64 * ASTR)             // 4608 per K / V array
#define AST_EL (2 * KV_AR)             // 9216 per stage (K + V)
#define A_KV0  (2 * AQ_ELE)            // 18432
#define A_TOTAL ((A_KV0 + 2 * AST_EL) * 2)   // 73728 bytes

__global__ __launch_bounds__(256, 2) void attn_mma() {
    extern __shared__ __half sma[];

    const int bh   = blockIdx.y;
    const int rblk = blockIdx.x;
    const int tid  = threadIdx.x;
    const int lane = tid & 31;
    const int wid  = tid >> 5;
    const int q0   = wid * 16;

    const size_t qbase = ((size_t)bh * SEQ + rblk * 128) * HD;
    const size_t kbase = (size_t)bh * SEQ * HD;
    const size_t vbase = (size_t)bh * HD * SEQ;

    const uint32_t sbase = smem_u32(sma);
    const uint32_t uQh = sbase;
    const uint32_t uQl = sbase + (uint32_t)AQ_ELE * 2;

#pragma unroll
    for (int it = 0; it < 4; ++it) {
        const int lin = it * 256 + tid;
        const int r = lin >> 3, d = (lin & 7) * 8;
        const uint32_t so = (uint32_t)(r * ASTR + d) * 2;
        cp16(uQh + so, g_Qhh + qbase + (size_t)r * HD + d);
        cp16(uQl + so, g_Qlh + qbase + (size_t)r * HD + d);
    }
    cp_commit();

    auto issue_kv = [&](int chunk, int st) {
        const int c0 = chunk * 64;
        const uint32_t skv = sbase + (uint32_t)(A_KV0 + st * AST_EL) * 2;
#pragma unroll
        for (int it = 0; it < 2; ++it) {
            const int lin = it * 256 + tid;
            const int r = lin >> 3, d = (lin & 7) * 8;
            const uint32_t so = (uint32_t)(r * ASTR + d) * 2;
            cp16(skv + so,                        g_Kf + kbase + (size_t)(c0 + r) * HD + d);
            cp16(skv + (uint32_t)KV_AR * 2 + so,  g_Vf + vbase + (size_t)r * SEQ + c0 + d);
        }
        cp_commit();
    };

    issue_kv(0, 0);

    float acc_o[8][4];
#pragma unroll
    for (int j = 0; j < 8; j++)
#pragma unroll
        for (int q = 0; q < 4; q++) acc_o[j][q] = 0.0f;
    float mi[2] = {-1e30f, -1e30f}, li[2] = {0.0f, 0.0f};

    const int a_row = lane & 15;
    const int a_kof = (lane >> 4) << 3;
    const int b_rof = ((lane >> 4) << 3) + (lane & 7);
    const int b_kof = ((lane >> 3) & 1) << 3;

    const int NC = SEQ / 64;   // 32
    for (int c = 0; c < NC; ++c) {
        const int st = c & 1;
        cp_wait0();
        __syncthreads();
        if (c + 1 < NC) issue_kv(c + 1, st ^ 1);

        const uint32_t skv = sbase + (uint32_t)(A_KV0 + st * AST_EL) * 2;
        const uint32_t uK = skv;
        const uint32_t uV = skv + (uint32_t)KV_AR * 2;

        float acc_s[8][4];
#pragma unroll
        for (int j = 0; j < 8; j++)
#pragma unroll
            for (int q = 0; q < 4; q++) acc_s[j][q] = 0.0f;

#pragma unroll
        for (int ks = 0; ks < 4; ++ks) {
            uint32_t ah[4], al[4];
            {
                const uint32_t off = (uint32_t)(((q0 + a_row) * ASTR + ks * 16 + a_kof) * 2);
                ldsm4(ah[0], ah[1], ah[2], ah[3], uQh + off);
                ldsm4(al[0], al[1], al[2], al[3], uQl + off);
            }
#pragma unroll
            for (int p = 0; p < 4; ++p) {
                uint32_t kh_[4];
                const uint32_t off = (uint32_t)(((p * 16 + b_rof) * ASTR + ks * 16 + b_kof) * 2);
                ldsm4(kh_[0], kh_[1], kh_[2], kh_[3], uK + off);
#pragma unroll
                for (int q = 0; q < 2; ++q) {
                    float* d = acc_s[p * 2 + q];
                    mma16816h(d, ah, &kh_[q * 2]);
                    mma16816h(d, al, &kh_[q * 2]);
                }
            }
        }

#pragma unroll
        for (int half = 0; half < 2; ++half) {
            float rmax = -1e30f;
#pragma unroll
            for (int nj = 0; nj < 8; ++nj)
#pragma unroll
                for (int t = 0; t < 2; ++t)
                    rmax = fmaxf(rmax, acc_s[nj][half * 2 + t]);
            rmax = fmaxf(rmax, __shfl_xor_sync(0xffffffffu, rmax, 1));
            rmax = fmaxf(rmax, __shfl_xor_sync(0xffffffffu, rmax, 2));
            const float mn = fmaxf(mi[half], rmax);
            float rsum = 0.0f;
#pragma unroll
            for (int nj = 0; nj < 8; ++nj)
#pragma unroll
                for (int t = 0; t < 2; ++t) {
                    const float e = ex2(acc_s[nj][half * 2 + t] - mn);
                    acc_s[nj][half * 2 + t] = e;
                    rsum += e;
                }
            rsum += __shfl_xor_sync(0xffffffffu, rsum, 1);
            rsum += __shfl_xor_sync(0xffffffffu, rsum, 2);
            const float alpha = ex2(mi[half] - mn);
            li[half] = li[half] * alpha + rsum;
            mi[half] = mn;
#pragma unroll
            for (int nj = 0; nj < 8; ++nj)
#pragma unroll
                for (int t = 0; t < 2; ++t) acc_o[nj][half * 2 + t] *= alpha;
        }

#pragma unroll
        for (int ks = 0; ks < 4; ++ks) {
            uint32_t ph[4], pl[4];
            split_pack_h(acc_s[2 * ks][0],     acc_s[2 * ks][1],     ph[0], pl[0]);
            split_pack_h(acc_s[2 * ks][2],     acc_s[2 * ks][3],     ph[1], pl[1]);
            split_pack_h(acc_s[2 * ks + 1][0], acc_s[2 * ks + 1][1], ph[2], pl[2]);
            split_pack_h(acc_s[2 * ks + 1][2], acc_s[2 * ks + 1][3], ph[3], pl[3]);
#pragma unroll
            for (int p = 0; p < 4; ++p) {
                uint32_t vh_[4];
                const uint32_t off = (uint32_t)(((p * 16 + b_rof) * ASTR + ks * 16 + b_kof) * 2);
                ldsm4(vh_[0], vh_[1], vh_[2], vh_[3], uV + off);
#pragma unroll
                for (int q = 0; q < 2; ++q) {
                    float* d = acc_o[p * 2 + q];
                    mma16816h(d, ph, &vh_[q * 2]);
                    mma16816h(d, pl, &vh_[q * 2]);
                }
            }
        }
    }

    const int b_ = bh >> 4, h = bh & 15;
#pragma unroll
    for (int half = 0; half < 2; ++half) {
        const float inv = 1.0f / li[half];
        const int row = rblk * 128 + q0 + (lane >> 2) + half * 8;
        const size_t mrow = ((size_t)b_ * SEQ + row) * DIM + h * HD;
#pragma unroll
        for (int nj = 0; nj < 8; ++nj) {
            const float o0 = acc_o[nj][half * 2 + 0] * inv;
            const float o1 = acc_o[nj][half * 2 + 1] * inv;
            __nv_bfloat16 h0, l0, h1, l1;
            split2(o0, h0, l0); split2(o1, h1, l1);
            const int cc = nj * 8 + (lane & 3) * 2;
            *(__nv_bfloat162*)(g_oh + mrow + cc) = {h0, h1};
            *(__nv_bfloat162*)(g_ol + mrow + cc) = {l0, l1};
        }
    }
}

// ---------------------------------------------------------------------------

extern "C" void kernel_launch(void* const* d_in, const int* in_sizes, int n_in,
                              void* d_out, int out_size) {
    (void)in_sizes; (void)n_in; (void)out_size;
    const float* x  = (const float*)d_in[0];
    const float* Wq = (const float*)d_in[1];
    const float* Wk = (const float*)d_in[2];
    const float* Wv = (const float*)d_in[3];
    const float* Wo = (const float*)d_in[4];
    const float* bo = (const float*)d_in[5];
    float* out = (float*)d_out;

    cudaFuncSetAttribute(gemm_qkv, cudaFuncAttributeMaxDynamicSharedMemorySize, G0SM_BYTES);
    cudaFuncSetAttribute(gemm_out, cudaFuncAttributeMaxDynamicSharedMemorySize, GSM_BYTES);
    cudaFuncSetAttribute(attn_mma, cudaFuncAttributeMaxDynamicSharedMemorySize, A_TOTAL);

    __half *xfh, *xfl, *wf;
    __nv_bfloat16 *woh, *wol, *oh, *ol;
    cudaGetSymbolAddress((void**)&xfh, g_xfh);
    cudaGetSymbolAddress((void**)&xfl, g_xfl);
    cudaGetSymbolAddress((void**)&wf,  g_wf);
    cudaGetSymbolAddress((void**)&woh, g_woh);
    cudaGetSymbolAddress((void**)&wol, g_wol);
    cudaGetSymbolAddress((void**)&oh,  g_oh);
    cudaGetSymbolAddress((void**)&ol,  g_ol);

    split_x_kernel<<<MROWS * DIM / 1024, 256>>>(x);
    transpose_split4<<<dim3(32, 32, 4), dim3(32, 8)>>>(Wq, Wk, Wv, Wo);

    gemm_qkv<<<dim3(24, 64), 256, G0SM_BYTES>>>(xfh, xfl, wf);
    attn_mma<<<dim3(16, 64), 256, A_TOTAL>>>();
    gemm_out<<<dim3(8, 32), 256, GSM_BYTES>>>(oh, ol, woh, wol, out, bo);
}

// round 11
// speedup vs baseline: 1.4677x; 1.0348x over previous
#include <cuda_runtime.h>
#include <cuda_bf16.h>
#include <cuda_fp16.h>
#include <cstdint>

#define DIM    1024
#define HEADS  16
#define HD     64
#define BATCH  4
#define SEQ    2048
#define MROWS  (BATCH * SEQ)            // 8192
#define QKV_ELEMS (BATCH * HEADS * SEQ * HD)  // 8388608

// 0.125 * log2(e): folded into Q so softmax is pure exp2
#define SCALE_Q 0.18033688011112042f

// ---------------------------------------------------------------------------
// Scratch (allocation-free rule: __device__ globals) — all fp16 now
// ---------------------------------------------------------------------------
__device__ __half g_Qhh[QKV_ELEMS], g_Qlh[QKV_ELEMS];  // [b,h,n,d], pre-scaled, hi/lo
__device__ __half g_Kf[QKV_ELEMS];                     // [b,h,n,d]
__device__ __half g_Vf[QKV_ELEMS];                     // [b,h,d,n] (transposed)
__device__ __half g_xfh[MROWS * DIM], g_xfl[MROWS * DIM];   // x hi/lo
__device__ __half g_wf[3 * DIM * DIM];                      // {Wq,Wk,Wv}^T [n][k]
__device__ __half g_wof[DIM * DIM];                         // Wo^T [n][k]
__device__ __half g_ofh[MROWS * DIM], g_ofl[MROWS * DIM];   // attn out hi/lo [m][h*64+d]

// ---------------------------------------------------------------------------
// helpers
// ---------------------------------------------------------------------------
__device__ __forceinline__ uint32_t smem_u32(const void* p) {
    uint32_t a;
    asm("{ .reg .u64 t; cvta.to.shared.u64 t, %1; cvt.u32.u64 %0, t; }" : "=r"(a) : "l"(p));
    return a;
}
__device__ __forceinline__ void ldsm4(uint32_t& r0, uint32_t& r1, uint32_t& r2, uint32_t& r3,
                                      uint32_t addr) {
    asm volatile("ldmatrix.sync.aligned.m8n8.x4.shared.b16 {%0,%1,%2,%3}, [%4];"
                 : "=r"(r0), "=r"(r1), "=r"(r2), "=r"(r3) : "r"(addr));
}
__device__ __forceinline__ void mma16816h(float* d, const uint32_t* a, const uint32_t* b) {
    asm volatile(
        "mma.sync.aligned.m16n8k16.row.col.f32.f16.f16.f32 "
        "{%0,%1,%2,%3}, {%4,%5,%6,%7}, {%8,%9}, {%0,%1,%2,%3};"
        : "+f"(d[0]), "+f"(d[1]), "+f"(d[2]), "+f"(d[3])
        : "r"(a[0]), "r"(a[1]), "r"(a[2]), "r"(a[3]), "r"(b[0]), "r"(b[1]));
}
__device__ __forceinline__ void cp16(uint32_t saddr, const void* gptr) {
    asm volatile("cp.async.cg.shared.global [%0], [%1], 16;" :: "r"(saddr), "l"(gptr));
}
__device__ __forceinline__ void cp_commit() {
    asm volatile("cp.async.commit_group;" ::: "memory");
}
__device__ __forceinline__ void cp_wait0() {
    asm volatile("cp.async.wait_group 0;" ::: "memory");
}
__device__ __forceinline__ void cp_wait1() {
    asm volatile("cp.async.wait_group 1;" ::: "memory");
}
__device__ __forceinline__ float ex2(float x) {
    float y;
    asm("ex2.approx.ftz.f32 %0, %1;" : "=f"(y) : "f"(x));
    return y;
}
__device__ __forceinline__ void split2h(float v, __half& h, __half& l) {
    h = __float2half_rn(v);
    l = __float2half_rn(v - __half2float(h));
}
__device__ __forceinline__ void split_pack_h(float v0, float v1, uint32_t& ph, uint32_t& pl) {
    __half h0, l0, h1, l1;
    split2h(v0, h0, l0); split2h(v1, h1, l1);
    __half2 th = {h0, h1}, tl = {l0, l1};
    ph = *(uint32_t*)&th;
    pl = *(uint32_t*)&tl;
}

// ---------------------------------------------------------------------------
// Prep kernels
// ---------------------------------------------------------------------------
__global__ __launch_bounds__(256) void split_x_kernel(const float* __restrict__ x) {
    int i = (blockIdx.x * 256 + threadIdx.x) * 4;
    float4 v = *(const float4*)(x + i);
    __half h0, h1, h2, h3, l0, l1, l2, l3;
    split2h(v.x, h0, l0); split2h(v.y, h1, l1); split2h(v.z, h2, l2); split2h(v.w, h3, l3);
    *(__half2*)(g_xfh + i)     = {h0, h1};
    *(__half2*)(g_xfh + i + 2) = {h2, h3};
    *(__half2*)(g_xfl + i)     = {l0, l1};
    *(__half2*)(g_xfl + i + 2) = {l2, l3};
}

// z<3: Wq/Wk/Wv -> g_wf; z==3: Wo -> g_wof (all single fp16, transposed)
__global__ __launch_bounds__(256) void transpose_split4(const float* __restrict__ W0,
                                                        const float* __restrict__ W1,
                                                        const float* __restrict__ W2,
                                                        const float* __restrict__ W3) {
    __shared__ float t[32][33];
    const int z = blockIdx.z;
    const float* src = (z == 0) ? W0 : (z == 1) ? W1 : (z == 2) ? W2 : W3;
    __half* dst = (z < 3) ? (g_wf + (size_t)z * DIM * DIM) : g_wof;

    const int bx = blockIdx.x * 32;
    const int by = blockIdx.y * 32;
    const int x = threadIdx.x, y0 = threadIdx.y;
#pragma unroll
    for (int i = 0; i < 32; i += 8)
        t[y0 + i][x] = src[(by + y0 + i) * DIM + bx + x];
    __syncthreads();
#pragma unroll
    for (int i = 0; i < 32; i += 8) {
        float v = t[x][y0 + i];
        dst[(bx + y0 + i) * DIM + by + x] = __float2half_rn(v);
    }
}

// ---------------------------------------------------------------------------
// fp16 2-product GEMM (Ah·B + Al·B), cp.async 3-stage, BK=32, 2 CTAs/SM.
// MODE 0: QKV epilogue (Q hi/lo pre-scaled, K, V^T). MODE 1: out proj + bias.
// ---------------------------------------------------------------------------
#define GBK    32
#define GSTR   40
#define GARR   (128 * GSTR)            // 5120 elems
#define GSTAGE (3 * GARR)              // 15360 elems
#define GSM_BYTES (3 * GSTAGE * 2)     // 92160 (3 stages)

template <int MODE, int RB>
__global__ __launch_bounds__(256, 2) void gemm_f16(
    const __half* __restrict__ Ah, const __half* __restrict__ Al,
    const __half* __restrict__ B,
    float* __restrict__ outp, const float* __restrict__ bo) {
    extern __shared__ __half smq[];

    const int tid  = threadIdx.x;
    const int lane = tid & 31;
    const int wid  = tid >> 5;
    const int wm   = wid & 1;
    const int wn   = wid >> 1;
    const int col0 = blockIdx.x * 128;

    const __half* pB = B + (size_t)col0 * DIM;
    const uint32_t sbase = smem_u32(smq);

    const int a_row = (lane & 15);
    const int a_kof = (lane >> 4) << 3;
    const int b_rof = ((lane >> 4) << 3) + (lane & 7);
    const int b_kof = ((lane >> 3) & 1) << 3;

    for (int rb = 0; rb < RB; ++rb) {
        const int row0 = (blockIdx.y * RB + rb) * 128;
        const __half* pAh = Ah + (size_t)row0 * DIM;
        const __half* pAl = Al + (size_t)row0 * DIM;

        float acc[4][4][4];
#pragma unroll
        for (int i = 0; i < 4; i++)
#pragma unroll
            for (int j = 0; j < 4; j++)
#pragma unroll
                for (int q = 0; q < 4; q++) acc[i][j][q] = 0.0f;

        auto issue = [&](int c, int st) {
            const int k0 = c * GBK;
            const uint32_t sst = sbase + (uint32_t)(st * GSTAGE) * 2;
#pragma unroll
            for (int it = 0; it < 2; ++it) {
                const int lin = it * 256 + tid;   // 0..511 : 128 rows x 4 groups
                const int rr = lin >> 2;
                const int cg = (lin & 3) * 8;
                const uint32_t so = (uint32_t)(rr * GSTR + cg) * 2;
                const size_t go = (size_t)rr * DIM + k0 + cg;
                cp16(sst + so,                       pAh + go);
                cp16(sst + (uint32_t)GARR * 2 + so,  pAl + go);
                cp16(sst + (uint32_t)(2 * GARR) * 2 + so, pB + go);
            }
            cp_commit();
        };

        issue(0, 0);
        issue(1, 1);

        const int NC = DIM / GBK;   // 32
        for (int c = 0; c < NC; ++c) {
            if (c + 1 < NC) cp_wait1(); else cp_wait0();
            __syncthreads();
            if (c + 2 < NC) issue(c + 2, (c + 2) % 3);

            const uint32_t sA = sbase + (uint32_t)((c % 3) * GSTAGE) * 2;
            const uint32_t sAh = sA;
            const uint32_t sAl = sA + (uint32_t)GARR * 2;
            const uint32_t sB  = sA + (uint32_t)(2 * GARR) * 2;

#pragma unroll
            for (int ks = 0; ks < GBK / 16; ++ks) {
                uint32_t bf[2][4];
#pragma unroll
                for (int p = 0; p < 2; ++p) {
                    const uint32_t off =
                        (uint32_t)(((wn * 32 + p * 16 + b_rof) * GSTR + ks * 16 + b_kof) * 2);
                    ldsm4(bf[p][0], bf[p][1], bf[p][2], bf[p][3], sB + off);
                }
#pragma unroll
                for (int mi = 0; mi < 4; ++mi) {
                    uint32_t ah[4], al[4];
                    const uint32_t off =
                        (uint32_t)(((wm * 64 + mi * 16 + a_row) * GSTR + ks * 16 + a_kof) * 2);
                    ldsm4(ah[0], ah[1], ah[2], ah[3], sAh + off);
                    ldsm4(al[0], al[1], al[2], al[3], sAl + off);
#pragma unroll
                    for (int p = 0; p < 2; ++p)
#pragma unroll
                        for (int q = 0; q < 2; ++q) {
                            float* d = acc[mi][p * 2 + q];
                            mma16816h(d, ah, &bf[p][q * 2]);
                            mma16816h(d, al, &bf[p][q * 2]);
                        }
                }
            }
        }

#pragma unroll
        for (int mi = 0; mi < 4; ++mi) {
#pragma unroll
            for (int nj = 0; nj < 4; ++nj) {
                const int r = row0 + wm * 64 + mi * 16 + (lane >> 2);
                const int cgl = col0 + wn * 32 + nj * 8 + (lane & 3) * 2;
#pragma unroll
                for (int half = 0; half < 2; ++half) {
                    const int rr = r + half * 8;
                    float v0 = acc[mi][nj][half * 2 + 0];
                    float v1 = acc[mi][nj][half * 2 + 1];
                    if (MODE == 0) {
                        const int b_ = rr >> 11, n = rr & 2047;
                        const int wsel = cgl >> 10;
                        const int c1 = cgl & 1023;
                        const int h = c1 >> 6, d0 = c1 & 63;
                        if (wsel == 0) {
                            v0 *= SCALE_Q; v1 *= SCALE_Q;
                            __half h0, l0, h1, l1;
                            split2h(v0, h0, l0); split2h(v1, h1, l1);
                            const size_t o = ((size_t)(b_ * HEADS + h) * SEQ + n) * HD + d0;
                            *(__half2*)(g_Qhh + o) = {h0, h1};
                            *(__half2*)(g_Qlh + o) = {l0, l1};
                        } else if (wsel == 1) {
                            const size_t o = ((size_t)(b_ * HEADS + h) * SEQ + n) * HD + d0;
                            *(__half2*)(g_Kf + o) = {__float2half_rn(v0), __float2half_rn(v1)};
                        } else {
                            const size_t o = ((size_t)(b_ * HEADS + h) * HD + d0) * SEQ + n;
                            g_Vf[o]       = __float2half_rn(v0);
                            g_Vf[o + SEQ] = __float2half_rn(v1);
                        }
                    } else {
                        *(float2*)(outp + (size_t)rr * DIM + cgl) =
                            make_float2(v0 + bo[cgl], v1 + bo[cgl + 1]);
                    }
                }
            }
        }
        if (rb + 1 < RB) __syncthreads();
    }
}

// ---------------------------------------------------------------------------
// Flash attention, fp16 2-product (R9/R10 proven). Epilogue -> fp16 hi/lo.
// ---------------------------------------------------------------------------
#define ASTR   72
#define AQ_ELE (128 * ASTR)            // 9216 per Q array (halves)
#define KV_AR  (64 * ASTR)             // 4608 per K / V array
#define AST_EL (2 * KV_AR)             // 9216 per stage (K + V)
#define A_KV0  (2 * AQ_ELE)            // 18432
#define A_TOTAL ((A_KV0 + 2 * AST_EL) * 2)   // 73728 bytes

__global__ __launch_bounds__(256, 2) void attn_mma() {
    extern __shared__ __half sma[];

    const int bh   = blockIdx.y;
    const int rblk = blockIdx.x;
    const int tid  = threadIdx.x;
    const int lane = tid & 31;
    const int wid  = tid >> 5;
    const int q0   = wid * 16;

    const size_t qbase = ((size_t)bh * SEQ + rblk * 128) * HD;
    const size_t kbase = (size_t)bh * SEQ * HD;
    const size_t vbase = (size_t)bh * HD * SEQ;

    const uint32_t sbase = smem_u32(sma);
    const uint32_t uQh = sbase;
    const uint32_t uQl = sbase + (uint32_t)AQ_ELE * 2;

#pragma unroll
    for (int it = 0; it < 4; ++it) {
        const int lin = it * 256 + tid;
        const int r = lin >> 3, d = (lin & 7) * 8;
        const uint32_t so = (uint32_t)(r * ASTR + d) * 2;
        cp16(uQh + so, g_Qhh + qbase + (size_t)r * HD + d);
        cp16(uQl + so, g_Qlh + qbase + (size_t)r * HD + d);
    }
    cp_commit();

    auto issue_kv = [&](int chunk, int st) {
        const int c0 = chunk * 64;
        const uint32_t skv = sbase + (uint32_t)(A_KV0 + st * AST_EL) * 2;
#pragma unroll
        for (int it = 0; it < 2; ++it) {
            const int lin = it * 256 + tid;
            const int r = lin >> 3, d = (lin & 7) * 8;
            const uint32_t so = (uint32_t)(r * ASTR + d) * 2;
            cp16(skv + so,                        g_Kf + kbase + (size_t)(c0 + r) * HD + d);
            cp16(skv + (uint32_t)KV_AR * 2 + so,  g_Vf + vbase + (size_t)r * SEQ + c0 + d);
        }
        cp_commit();
    };

    issue_kv(0, 0);

    float acc_o[8][4];
#pragma unroll
    for (int j = 0; j < 8; j++)
#pragma unroll
        for (int q = 0; q < 4; q++) acc_o[j][q] = 0.0f;
    float mi[2] = {-1e30f, -1e30f}, li[2] = {0.0f, 0.0f};

    const int a_row = lane & 15;
    const int a_kof = (lane >> 4) << 3;
    const int b_rof = ((lane >> 4) << 3) + (lane & 7);
    const int b_kof = ((lane >> 3) & 1) << 3;

    const int NC = SEQ / 64;   // 32
    for (int c = 0; c < NC; ++c) {
        const int st = c & 1;
        cp_wait0();
        __syncthreads();
        if (c + 1 < NC) issue_kv(c + 1, st ^ 1);

        const uint32_t skv = sbase + (uint32_t)(A_KV0 + st * AST_EL) * 2;
        const uint32_t uK = skv;
        const uint32_t uV = skv + (uint32_t)KV_AR * 2;

        float acc_s[8][4];
#pragma unroll
        for (int j = 0; j < 8; j++)
#pragma unroll
            for (int q = 0; q < 4; q++) acc_s[j][q] = 0.0f;

#pragma unroll
        for (int ks = 0; ks < 4; ++ks) {
            uint32_t ah[4], al[4];
            {
                const uint32_t off = (uint32_t)(((q0 + a_row) * ASTR + ks * 16 + a_kof) * 2);
                ldsm4(ah[0], ah[1], ah[2], ah[3], uQh + off);
                ldsm4(al[0], al[1], al[2], al[3], uQl + off);
            }
#pragma unroll
            for (int p = 0; p < 4; ++p) {
                uint32_t kh_[4];
                const uint32_t off = (uint32_t)(((p * 16 + b_rof) * ASTR + ks * 16 + b_kof) * 2);
                ldsm4(kh_[0], kh_[1], kh_[2], kh_[3], uK + off);
#pragma unroll
                for (int q = 0; q < 2; ++q) {
                    float* d = acc_s[p * 2 + q];
                    mma16816h(d, ah, &kh_[q * 2]);
                    mma16816h(d, al, &kh_[q * 2]);
                }
            }
        }

#pragma unroll
        for (int half = 0; half < 2; ++half) {
            float rmax = -1e30f;
#pragma unroll
            for (int nj = 0; nj < 8; ++nj)
#pragma unroll
                for (int t = 0; t < 2; ++t)
                    rmax = fmaxf(rmax, acc_s[nj][half * 2 + t]);
            rmax = fmaxf(rmax, __shfl_xor_sync(0xffffffffu, rmax, 1));
            rmax = fmaxf(rmax, __shfl_xor_sync(0xffffffffu, rmax, 2));
            const float mn = fmaxf(mi[half], rmax);
            float rsum = 0.0f;
#pragma unroll
            for (int nj = 0; nj < 8; ++nj)
#pragma unroll
                for (int t = 0; t < 2; ++t) {
                    const float e = ex2(acc_s[nj][half * 2 + t] - mn);
                    acc_s[nj][half * 2 + t] = e;
                    rsum += e;
                }
            rsum += __shfl_xor_sync(0xffffffffu, rsum, 1);
            rsum += __shfl_xor_sync(0xffffffffu, rsum, 2);
            const float alpha = ex2(mi[half] - mn);
            li[half] = li[half] * alpha + rsum;
            mi[half] = mn;
#pragma unroll
            for (int nj = 0; nj < 8; ++nj)
#pragma unroll
                for (int t = 0; t < 2; ++t) acc_o[nj][half * 2 + t] *= alpha;
        }

#pragma unroll
        for (int ks = 0; ks < 4; ++ks) {
            uint32_t ph[4], pl[4];
            split_pack_h(acc_s[2 * ks][0],     acc_s[2 * ks][1],     ph[0], pl[0]);
            split_pack_h(acc_s[2 * ks][2],     acc_s[2 * ks][3],     ph[1], pl[1]);
            split_pack_h(acc_s[2 * ks + 1][0], acc_s[2 * ks + 1][1], ph[2], pl[2]);
            split_pack_h(acc_s[2 * ks + 1][2], acc_s[2 * ks + 1][3], ph[3], pl[3]);
#pragma unroll
            for (int p = 0; p < 4; ++p) {
                uint32_t vh_[4];
                const uint32_t off = (uint32_t)(((p * 16 + b_rof) * ASTR + ks * 16 + b_kof) * 2);
                ldsm4(vh_[0], vh_[1], vh_[2], vh_[3], uV + off);
#pragma unroll
                for (int q = 0; q < 2; ++q) {
                    float* d = acc_o[p * 2 + q];
                    mma16816h(d, ph, &vh_[q * 2]);
                    mma16816h(d, pl, &vh_[q * 2]);
                }
            }
        }
    }

    // Epilogue: normalize, split fp16 hi/lo for proj GEMM
    const int b_ = bh >> 4, h = bh & 15;
#pragma unroll
    for (int half = 0; half < 2; ++half) {
        const float inv = 1.0f / li[half];
        const int row = rblk * 128 + q0 + (lane >> 2) + half * 8;
        const size_t mrow = ((size_t)b_ * SEQ + row) * DIM + h * HD;
#pragma unroll
        for (int nj = 0; nj < 8; ++nj) {
            const float o0 = acc_o[nj][half * 2 + 0] * inv;
            const float o1 = acc_o[nj][half * 2 + 1] * inv;
            __half h0, l0, h1, l1;
            split2h(o0, h0, l0); split2h(o1, h1, l1);
            const int cc = nj * 8 + (lane & 3) * 2;
            *(__half2*)(g_ofh + mrow + cc) = {h0, h1};
            *(__half2*)(g_ofl + mrow + cc) = {l0, l1};
        }
    }
}

// ---------------------------------------------------------------------------

extern "C" void kernel_launch(void* const* d_in, const int* in_sizes, int n_in,
                              void* d_out, int out_size) {
    (void)in_sizes; (void)n_in; (void)out_size;
    const float* x  = (const float*)d_in[0];
    const float* Wq = (const float*)d_in[1];
    const float* Wk = (const float*)d_in[2];
    const float* Wv = (const float*)d_in[3];
    const float* Wo = (const float*)d_in[4];
    const float* bo = (const float*)d_in[5];
    float* out = (float*)d_out;

    cudaFuncSetAttribute((const void*)gemm_f16<0, 1>,
                         cudaFuncAttributeMaxDynamicSharedMemorySize, GSM_BYTES);
    cudaFuncSetAttribute((const void*)gemm_f16<1, 2>,
                         cudaFuncAttributeMaxDynamicSharedMemorySize, GSM_BYTES);
    cudaFuncSetAttribute((const void*)attn_mma,
                         cudaFuncAttributeMaxDynamicSharedMemorySize, A_TOTAL);

    __half *xfh, *xfl, *wf, *wof, *ofh, *ofl;
    cudaGetSymbolAddress((void**)&xfh, g_xfh);
    cudaGetSymbolAddress((void**)&xfl, g_xfl);
    cudaGetSymbolAddress((void**)&wf,  g_wf);
    cudaGetSymbolAddress((void**)&wof, g_wof);
    cudaGetSymbolAddress((void**)&ofh, g_ofh);
    cudaGetSymbolAddress((void**)&ofl, g_ofl);

    split_x_kernel<<<MROWS * DIM / 1024, 256>>>(x);
    transpose_split4<<<dim3(32, 32, 4), dim3(32, 8)>>>(Wq, Wk, Wv, Wo);

    gemm_f16<0, 1><<<dim3(24, 64), 256, GSM_BYTES>>>(xfh, xfl, wf, nullptr, nullptr);
    attn_mma<<<dim3(16, 64), 256, A_TOTAL>>>();
    gemm_f16<1, 2><<<dim3(8, 32), 256, GSM_BYTES>>>(ofh, ofl, wof, out, bo);
}

// round 12
// speedup vs baseline: 1.8972x; 1.2927x over previous
#include <cuda_runtime.h>
#include <cuda_fp16.h>
#include <cstdint>

#define DIM    1024
#define HEADS  16
#define HD     64
#define BATCH  4
#define SEQ    2048
#define MROWS  (BATCH * SEQ)            // 8192
#define QKV_ELEMS (BATCH * HEADS * SEQ * HD)  // 8388608

// 0.125 * log2(e): folded into Q so softmax is pure exp2
#define SCALE_Q 0.18033688011112042f

// ---------------------------------------------------------------------------
// Scratch (allocation-free rule: __device__ globals) — all fp16
// ---------------------------------------------------------------------------
__device__ __half g_Qhh[QKV_ELEMS], g_Qlh[QKV_ELEMS];  // [b,h,n,d], pre-scaled, hi/lo
__device__ __half g_Kf[QKV_ELEMS];                     // [b,h,n,d]
__device__ __half g_Vf[QKV_ELEMS];                     // [b,h,d,n] (transposed)
__device__ __half g_xf[MROWS * DIM];                   // x single fp16
__device__ __half g_wf[3 * DIM * DIM];                 // {Wq,Wk,Wv}^T [n][k]
__device__ __half g_wof[DIM * DIM];                    // Wo^T [n][k]
__device__ __half g_of[MROWS * DIM];                   // attn out single fp16 [m][h*64+d]

// ---------------------------------------------------------------------------
// helpers
// ---------------------------------------------------------------------------
__device__ __forceinline__ uint32_t smem_u32(const void* p) {
    uint32_t a;
    asm("{ .reg .u64 t; cvta.to.shared.u64 t, %1; cvt.u32.u64 %0, t; }" : "=r"(a) : "l"(p));
    return a;
}
__device__ __forceinline__ void ldsm4(uint32_t& r0, uint32_t& r1, uint32_t& r2, uint32_t& r3,
                                      uint32_t addr) {
    asm volatile("ldmatrix.sync.aligned.m8n8.x4.shared.b16 {%0,%1,%2,%3}, [%4];"
                 : "=r"(r0), "=r"(r1), "=r"(r2), "=r"(r3) : "r"(addr));
}
__device__ __forceinline__ void mma16816h(float* d, const uint32_t* a, const uint32_t* b) {
    asm volatile(
        "mma.sync.aligned.m16n8k16.row.col.f32.f16.f16.f32 "
        "{%0,%1,%2,%3}, {%4,%5,%6,%7}, {%8,%9}, {%0,%1,%2,%3};"
        : "+f"(d[0]), "+f"(d[1]), "+f"(d[2]), "+f"(d[3])
        : "r"(a[0]), "r"(a[1]), "r"(a[2]), "r"(a[3]), "r"(b[0]), "r"(b[1]));
}
__device__ __forceinline__ void cp16(uint32_t saddr, const void* gptr) {
    asm volatile("cp.async.cg.shared.global [%0], [%1], 16;" :: "r"(saddr), "l"(gptr));
}
__device__ __forceinline__ void cp_commit() {
    asm volatile("cp.async.commit_group;" ::: "memory");
}
__device__ __forceinline__ void cp_wait0() {
    asm volatile("cp.async.wait_group 0;" ::: "memory");
}
__device__ __forceinline__ void cp_wait1() {
    asm volatile("cp.async.wait_group 1;" ::: "memory");
}
__device__ __forceinline__ float ex2(float x) {
    float y;
    asm("ex2.approx.ftz.f32 %0, %1;" : "=f"(y) : "f"(x));
    return y;
}
__device__ __forceinline__ void split2h(float v, __half& h, __half& l) {
    h = __float2half_rn(v);
    l = __float2half_rn(v - __half2float(h));
}
__device__ __forceinline__ void split_pack_h(float v0, float v1, uint32_t& ph, uint32_t& pl) {
    __half h0, l0, h1, l1;
    split2h(v0, h0, l0); split2h(v1, h1, l1);
    __half2 th = {h0, h1}, tl = {l0, l1};
    ph = *(uint32_t*)&th;
    pl = *(uint32_t*)&tl;
}

// ---------------------------------------------------------------------------
// Prep kernels
// ---------------------------------------------------------------------------
__global__ __launch_bounds__(256) void conv_x_kernel(const float* __restrict__ x) {
    int i = (blockIdx.x * 256 + threadIdx.x) * 4;
    float4 v = *(const float4*)(x + i);
    *(__half2*)(g_xf + i)     = {__float2half_rn(v.x), __float2half_rn(v.y)};
    *(__half2*)(g_xf + i + 2) = {__float2half_rn(v.z), __float2half_rn(v.w)};
}

// z<3: Wq/Wk/Wv -> g_wf; z==3: Wo -> g_wof (all single fp16, transposed)
__global__ __launch_bounds__(256) void transpose_conv4(const float* __restrict__ W0,
                                                       const float* __restrict__ W1,
                                                       const float* __restrict__ W2,
                                                       const float* __restrict__ W3) {
    __shared__ float t[32][33];
    const int z = blockIdx.z;
    const float* src = (z == 0) ? W0 : (z == 1) ? W1 : (z == 2) ? W2 : W3;
    __half* dst = (z < 3) ? (g_wf + (size_t)z * DIM * DIM) : g_wof;

    const int bx = blockIdx.x * 32;
    const int by = blockIdx.y * 32;
    const int x = threadIdx.x, y0 = threadIdx.y;
#pragma unroll
    for (int i = 0; i < 32; i += 8)
        t[y0 + i][x] = src[(by + y0 + i) * DIM + bx + x];
    __syncthreads();
#pragma unroll
    for (int i = 0; i < 32; i += 8) {
        float v = t[x][y0 + i];
        dst[(bx + y0 + i) * DIM + by + x] = __float2half_rn(v);
    }
}

// ---------------------------------------------------------------------------
// Plain fp16 GEMM (C = A·B^T layout-wise), cp.async 3-stage, BK=32, 2 CTAs/SM.
// MODE 0: QKV epilogue (Q hi/lo pre-scaled, K, V^T). MODE 1: out proj + bias.
// ---------------------------------------------------------------------------
#define GBK    32
#define GSTR   40
#define GARR   (128 * GSTR)            // 5120 elems
#define GSTAGE (2 * GARR)              // 10240 elems (A + B)
#define GSM_BYTES (3 * GSTAGE * 2)     // 61440 (3 stages)

template <int MODE, int RB>
__global__ __launch_bounds__(256, 2) void gemm_f16(
    const __half* __restrict__ A, const __half* __restrict__ B,
    float* __restrict__ outp, const float* __restrict__ bo) {
    extern __shared__ __half smq[];

    const int tid  = threadIdx.x;
    const int lane = tid & 31;
    const int wid  = tid >> 5;
    const int wm   = wid & 1;
    const int wn   = wid >> 1;
    const int col0 = blockIdx.x * 128;

    const __half* pB = B + (size_t)col0 * DIM;
    const uint32_t sbase = smem_u32(smq);

    const int a_row = (lane & 15);
    const int a_kof = (lane >> 4) << 3;
    const int b_rof = ((lane >> 4) << 3) + (lane & 7);
    const int b_kof = ((lane >> 3) & 1) << 3;

    for (int rb = 0; rb < RB; ++rb) {
        const int row0 = (blockIdx.y * RB + rb) * 128;
        const __half* pA = A + (size_t)row0 * DIM;

        float acc[4][4][4];
#pragma unroll
        for (int i = 0; i < 4; i++)
#pragma unroll
            for (int j = 0; j < 4; j++)
#pragma unroll
                for (int q = 0; q < 4; q++) acc[i][j][q] = 0.0f;

        auto issue = [&](int c, int st) {
            const int k0 = c * GBK;
            const uint32_t sst = sbase + (uint32_t)(st * GSTAGE) * 2;
#pragma unroll
            for (int it = 0; it < 2; ++it) {
                const int lin = it * 256 + tid;   // 0..511 : 128 rows x 4 groups
                const int rr = lin >> 2;
                const int cg = (lin & 3) * 8;
                const uint32_t so = (uint32_t)(rr * GSTR + cg) * 2;
                const size_t go = (size_t)rr * DIM + k0 + cg;
                cp16(sst + so,                      pA + go);
                cp16(sst + (uint32_t)GARR * 2 + so, pB + go);
            }
            cp_commit();
        };

        issue(0, 0);
        issue(1, 1);

        const int NC = DIM / GBK;   // 32
        for (int c = 0; c < NC; ++c) {
            if (c + 1 < NC) cp_wait1(); else cp_wait0();
            __syncthreads();
            if (c + 2 < NC) issue(c + 2, (c + 2) % 3);

            const uint32_t sA = sbase + (uint32_t)((c % 3) * GSTAGE) * 2;
            const uint32_t sB = sA + (uint32_t)GARR * 2;

#pragma unroll
            for (int ks = 0; ks < GBK / 16; ++ks) {
                uint32_t bf[2][4];
#pragma unroll
                for (int p = 0; p < 2; ++p) {
                    const uint32_t off =
                        (uint32_t)(((wn * 32 + p * 16 + b_rof) * GSTR + ks * 16 + b_kof) * 2);
                    ldsm4(bf[p][0], bf[p][1], bf[p][2], bf[p][3], sB + off);
                }
#pragma unroll
                for (int mi = 0; mi < 4; ++mi) {
                    uint32_t af[4];
                    const uint32_t off =
                        (uint32_t)(((wm * 64 + mi * 16 + a_row) * GSTR + ks * 16 + a_kof) * 2);
                    ldsm4(af[0], af[1], af[2], af[3], sA + off);
#pragma unroll
                    for (int p = 0; p < 2; ++p)
#pragma unroll
                        for (int q = 0; q < 2; ++q)
                            mma16816h(acc[mi][p * 2 + q], af, &bf[p][q * 2]);
                }
            }
        }

#pragma unroll
        for (int mi = 0; mi < 4; ++mi) {
#pragma unroll
            for (int nj = 0; nj < 4; ++nj) {
                const int r = row0 + wm * 64 + mi * 16 + (lane >> 2);
                const int cgl = col0 + wn * 32 + nj * 8 + (lane & 3) * 2;
#pragma unroll
                for (int half = 0; half < 2; ++half) {
                    const int rr = r + half * 8;
                    float v0 = acc[mi][nj][half * 2 + 0];
                    float v1 = acc[mi][nj][half * 2 + 1];
                    if (MODE == 0) {
                        const int b_ = rr >> 11, n = rr & 2047;
                        const int wsel = cgl >> 10;
                        const int c1 = cgl & 1023;
                        const int h = c1 >> 6, d0 = c1 & 63;
                        if (wsel == 0) {
                            v0 *= SCALE_Q; v1 *= SCALE_Q;
                            __half h0, l0, h1, l1;
                            split2h(v0, h0, l0); split2h(v1, h1, l1);
                            const size_t o = ((size_t)(b_ * HEADS + h) * SEQ + n) * HD + d0;
                            *(__half2*)(g_Qhh + o) = {h0, h1};
                            *(__half2*)(g_Qlh + o) = {l0, l1};
                        } else if (wsel == 1) {
                            const size_t o = ((size_t)(b_ * HEADS + h) * SEQ + n) * HD + d0;
                            *(__half2*)(g_Kf + o) = {__float2half_rn(v0), __float2half_rn(v1)};
                        } else {
                            const size_t o = ((size_t)(b_ * HEADS + h) * HD + d0) * SEQ + n;
                            g_Vf[o]       = __float2half_rn(v0);
                            g_Vf[o + SEQ] = __float2half_rn(v1);
                        }
                    } else {
                        *(float2*)(outp + (size_t)rr * DIM + cgl) =
                            make_float2(v0 + bo[cgl], v1 + bo[cgl + 1]);
                    }
                }
            }
        }
        if (rb + 1 < RB) __syncthreads();
    }
}

// ---------------------------------------------------------------------------
// Flash attention, fp16 2-product (R9-R11 proven). Epilogue -> single fp16 O.
// ---------------------------------------------------------------------------
#define ASTR   72
#define AQ_ELE (128 * ASTR)            // 9216 per Q array (halves)
#define KV_AR  (64 * ASTR)             // 4608 per K / V array
#define AST_EL (2 * KV_AR)             // 9216 per stage (K + V)
#define A_KV0  (2 * AQ_ELE)            // 18432
#define A_TOTAL ((A_KV0 + 2 * AST_EL) * 2)   // 73728 bytes

__global__ __launch_bounds__(256, 2) void attn_mma() {
    extern __shared__ __half sma[];

    const int bh   = blockIdx.y;
    const int rblk = blockIdx.x;
    const int tid  = threadIdx.x;
    const int lane = tid & 31;
    const int wid  = tid >> 5;
    const int q0   = wid * 16;

    const size_t qbase = ((size_t)bh * SEQ + rblk * 128) * HD;
    const size_t kbase = (size_t)bh * SEQ * HD;
    const size_t vbase = (size_t)bh * HD * SEQ;

    const uint32_t sbase = smem_u32(sma);
    const uint32_t uQh = sbase;
    const uint32_t uQl = sbase + (uint32_t)AQ_ELE * 2;

#pragma unroll
    for (int it = 0; it < 4; ++it) {
        const int lin = it * 256 + tid;
        const int r = lin >> 3, d = (lin & 7) * 8;
        const uint32_t so = (uint32_t)(r * ASTR + d) * 2;
        cp16(uQh + so, g_Qhh + qbase + (size_t)r * HD + d);
        cp16(uQl + so, g_Qlh + qbase + (size_t)r * HD + d);
    }
    cp_commit();

    auto issue_kv = [&](int chunk, int st) {
        const int c0 = chunk * 64;
        const uint32_t skv = sbase + (uint32_t)(A_KV0 + st * AST_EL) * 2;
#pragma unroll
        for (int it = 0; it < 2; ++it) {
            const int lin = it * 256 + tid;
            const int r = lin >> 3, d = (lin & 7) * 8;
            const uint32_t so = (uint32_t)(r * ASTR + d) * 2;
            cp16(skv + so,                        g_Kf + kbase + (size_t)(c0 + r) * HD + d);
            cp16(skv + (uint32_t)KV_AR * 2 + so,  g_Vf + vbase + (size_t)r * SEQ + c0 + d);
        }
        cp_commit();
    };

    issue_kv(0, 0);

    float acc_o[8][4];
#pragma unroll
    for (int j = 0; j < 8; j++)
#pragma unroll
        for (int q = 0; q < 4; q++) acc_o[j][q] = 0.0f;
    float mi[2] = {-1e30f, -1e30f}, li[2] = {0.0f, 0.0f};

    const int a_row = lane & 15;
    const int a_kof = (lane >> 4) << 3;
    const int b_rof = ((lane >> 4) << 3) + (lane & 7);
    const int b_kof = ((lane >> 3) & 1) << 3;

    const int NC = SEQ / 64;   // 32
    for (int c = 0; c < NC; ++c) {
        const int st = c & 1;
        cp_wait0();
        __syncthreads();
        if (c + 1 < NC) issue_kv(c + 1, st ^ 1);

        const uint32_t skv = sbase + (uint32_t)(A_KV0 + st * AST_EL) * 2;
        const uint32_t uK = skv;
        const uint32_t uV = skv + (uint32_t)KV_AR * 2;

        float acc_s[8][4];
#pragma unroll
        for (int j = 0; j < 8; j++)
#pragma unroll
            for (int q = 0; q < 4; q++) acc_s[j][q] = 0.0f;

#pragma unroll
        for (int ks = 0; ks < 4; ++ks) {
            uint32_t ah[4], al[4];
            {
                const uint32_t off = (uint32_t)(((q0 + a_row) * ASTR + ks * 16 + a_kof) * 2);
                ldsm4(ah[0], ah[1], ah[2], ah[3], uQh + off);
                ldsm4(al[0], al[1], al[2], al[3], uQl + off);
            }
#pragma unroll
            for (int p = 0; p < 4; ++p) {
                uint32_t kh_[4];
                const uint32_t off = (uint32_t)(((p * 16 + b_rof) * ASTR + ks * 16 + b_kof) * 2);
                ldsm4(kh_[0], kh_[1], kh_[2], kh_[3], uK + off);
#pragma unroll
                for (int q = 0; q < 2; ++q) {
                    float* d = acc_s[p * 2 + q];
                    mma16816h(d, ah, &kh_[q * 2]);
                    mma16816h(d, al, &kh_[q * 2]);
                }
            }
        }

#pragma unroll
        for (int half = 0; half < 2; ++half) {
            float rmax = -1e30f;
#pragma unroll
            for (int nj = 0; nj < 8; ++nj)
#pragma unroll
                for (int t = 0; t < 2; ++t)
                    rmax = fmaxf(rmax, acc_s[nj][half * 2 + t]);
            rmax = fmaxf(rmax, __shfl_xor_sync(0xffffffffu, rmax, 1));
            rmax = fmaxf(rmax, __shfl_xor_sync(0xffffffffu, rmax, 2));
            const float mn = fmaxf(mi[half], rmax);
            float rsum = 0.0f;
#pragma unroll
            for (int nj = 0; nj < 8; ++nj)
#pragma unroll
                for (int t = 0; t < 2; ++t) {
                    const float e = ex2(acc_s[nj][half * 2 + t] - mn);
                    acc_s[nj][half * 2 + t] = e;
                    rsum += e;
                }
            rsum += __shfl_xor_sync(0xffffffffu, rsum, 1);
            rsum += __shfl_xor_sync(0xffffffffu, rsum, 2);
            const float alpha = ex2(mi[half] - mn);
            li[half] = li[half] * alpha + rsum;
            mi[half] = mn;
#pragma unroll
            for (int nj = 0; nj < 8; ++nj)
#pragma unroll
                for (int t = 0; t < 2; ++t) acc_o[nj][half * 2 + t] *= alpha;
        }

#pragma unroll
        for (int ks = 0; ks < 4; ++ks) {
            uint32_t ph[4], pl[4];
            split_pack_h(acc_s[2 * ks][0],     acc_s[2 * ks][1],     ph[0], pl[0]);
            split_pack_h(acc_s[2 * ks][2],     acc_s[2 * ks][3],     ph[1], pl[1]);
            split_pack_h(acc_s[2 * ks + 1][0], acc_s[2 * ks + 1][1], ph[2], pl[2]);
            split_pack_h(acc_s[2 * ks + 1][2], acc_s[2 * ks + 1][3], ph[3], pl[3]);
#pragma unroll
            for (int p = 0; p < 4; ++p) {
                uint32_t vh_[4];
                const uint32_t off = (uint32_t)(((p * 16 + b_rof) * ASTR + ks * 16 + b_kof) * 2);
                ldsm4(vh_[0], vh_[1], vh_[2], vh_[3], uV + off);
#pragma unroll
                for (int q = 0; q < 2; ++q) {
                    float* d = acc_o[p * 2 + q];
                    mma16816h(d, ph, &vh_[q * 2]);
                    mma16816h(d, pl, &vh_[q * 2]);
                }
            }
        }
    }

    // Epilogue: normalize, write single fp16 O for proj GEMM
    const int b_ = bh >> 4, h = bh & 15;
#pragma unroll
    for (int half = 0; half < 2; ++half) {
        const float inv = 1.0f / li[half];
        const int row = rblk * 128 + q0 + (lane >> 2) + half * 8;
        const size_t mrow = ((size_t)b_ * SEQ + row) * DIM + h * HD;
#pragma unroll
        for (int nj = 0; nj < 8; ++nj) {
            const float o0 = acc_o[nj][half * 2 + 0] * inv;
            const float o1 = acc_o[nj][half * 2 + 1] * inv;
            const int cc = nj * 8 + (lane & 3) * 2;
            *(__half2*)(g_of + mrow + cc) = {__float2half_rn(o0), __float2half_rn(o1)};
        }
    }
}

// ---------------------------------------------------------------------------

extern "C" void kernel_launch(void* const* d_in, const int* in_sizes, int n_in,
                              void* d_out, int out_size) {
    (void)in_sizes; (void)n_in; (void)out_size;
    const float* x  = (const float*)d_in[0];
    const float* Wq = (const float*)d_in[1];
    const float* Wk = (const float*)d_in[2];
    const float* Wv = (const float*)d_in[3];
    const float* Wo = (const float*)d_in[4];
    const float* bo = (const float*)d_in[5];
    float* out = (float*)d_out;

    cudaFuncSetAttribute((const void*)gemm_f16<0, 1>,
                         cudaFuncAttributeMaxDynamicSharedMemorySize, GSM_BYTES);
    cudaFuncSetAttribute((const void*)gemm_f16<1, 2>,
                         cudaFuncAttributeMaxDynamicSharedMemorySize, GSM_BYTES);
    cudaFuncSetAttribute((const void*)attn_mma,
                         cudaFuncAttributeMaxDynamicSharedMemorySize, A_TOTAL);

    __half *xf, *wf, *wof, *of;
    cudaGetSymbolAddress((void**)&xf,  g_xf);
    cudaGetSymbolAddress((void**)&wf,  g_wf);
    cudaGetSymbolAddress((void**)&wof, g_wof);
    cudaGetSymbolAddress((void**)&of,  g_of);

    conv_x_kernel<<<MROWS * DIM / 1024, 256>>>(x);
    transpose_conv4<<<dim3(32, 32, 4), dim3(32, 8)>>>(Wq, Wk, Wv, Wo);

    gemm_f16<0, 1><<<dim3(24, 64), 256, GSM_BYTES>>>(xf, wf, nullptr, nullptr);
    attn_mma<<<dim3(16, 64), 256, A_TOTAL>>>();
    gemm_f16<1, 2><<<dim3(8, 32), 256, GSM_BYTES>>>(of, wof, out, bo);
}

// round 13
// speedup vs baseline: 2.4375x; 1.2848x over previous
#include <cuda_runtime.h>
#include <cuda_fp16.h>
#include <cstdint>

#define DIM    1024
#define HEADS  16
#define HD     64
#define BATCH  4
#define SEQ    2048
#define MROWS  (BATCH * SEQ)            // 8192
#define QKV_ELEMS (BATCH * HEADS * SEQ * HD)  // 8388608

// 0.125 * log2(e): folded into Q so softmax is pure exp2
#define SCALE_Q 0.18033688011112042f

// ---------------------------------------------------------------------------
// Scratch (allocation-free rule: __device__ globals) — all fp16 single
// ---------------------------------------------------------------------------
__device__ __half g_Qf[QKV_ELEMS];                 // [b,h,n,d], pre-scaled
__device__ __half g_Kf[QKV_ELEMS];                 // [b,h,n,d]
__device__ __half g_Vf[QKV_ELEMS];                 // [b,h,d,n] (transposed)
__device__ __half g_xf[MROWS * DIM];               // x
__device__ __half g_wf[3 * DIM * DIM];             // {Wq,Wk,Wv}^T [n][k]
__device__ __half g_wof[DIM * DIM];                // Wo^T [n][k]
__device__ __half g_of[MROWS * DIM];               // attn out [m][h*64+d]

// ---------------------------------------------------------------------------
// helpers
// ---------------------------------------------------------------------------
__device__ __forceinline__ uint32_t smem_u32(const void* p) {
    uint32_t a;
    asm("{ .reg .u64 t; cvta.to.shared.u64 t, %1; cvt.u32.u64 %0, t; }" : "=r"(a) : "l"(p));
    return a;
}
__device__ __forceinline__ void ldsm4(uint32_t& r0, uint32_t& r1, uint32_t& r2, uint32_t& r3,
                                      uint32_t addr) {
    asm volatile("ldmatrix.sync.aligned.m8n8.x4.shared.b16 {%0,%1,%2,%3}, [%4];"
                 : "=r"(r0), "=r"(r1), "=r"(r2), "=r"(r3) : "r"(addr));
}
__device__ __forceinline__ void mma16816h(float* d, const uint32_t* a, const uint32_t* b) {
    asm volatile(
        "mma.sync.aligned.m16n8k16.row.col.f32.f16.f16.f32 "
        "{%0,%1,%2,%3}, {%4,%5,%6,%7}, {%8,%9}, {%0,%1,%2,%3};"
        : "+f"(d[0]), "+f"(d[1]), "+f"(d[2]), "+f"(d[3])
        : "r"(a[0]), "r"(a[1]), "r"(a[2]), "r"(a[3]), "r"(b[0]), "r"(b[1]));
}
__device__ __forceinline__ void cp16(uint32_t saddr, const void* gptr) {
    asm volatile("cp.async.cg.shared.global [%0], [%1], 16;" :: "r"(saddr), "l"(gptr));
}
__device__ __forceinline__ void cp_commit() {
    asm volatile("cp.async.commit_group;" ::: "memory");
}
__device__ __forceinline__ void cp_wait0() {
    asm volatile("cp.async.wait_group 0;" ::: "memory");
}
__device__ __forceinline__ void cp_wait1() {
    asm volatile("cp.async.wait_group 1;" ::: "memory");
}
__device__ __forceinline__ float ex2(float x) {
    float y;
    asm("ex2.approx.ftz.f32 %0, %1;" : "=f"(y) : "f"(x));
    return y;
}
__device__ __forceinline__ uint32_t pack_h2(float v0, float v1) {
    __half2 t = {__float2half_rn(v0), __float2half_rn(v1)};
    return *(uint32_t*)&t;
}

// ---------------------------------------------------------------------------
// Prep kernels
// ---------------------------------------------------------------------------
__global__ __launch_bounds__(256) void conv_x_kernel(const float* __restrict__ x) {
    int i = (blockIdx.x * 256 + threadIdx.x) * 4;
    float4 v = *(const float4*)(x + i);
    *(__half2*)(g_xf + i)     = {__float2half_rn(v.x), __float2half_rn(v.y)};
    *(__half2*)(g_xf + i + 2) = {__float2half_rn(v.z), __float2half_rn(v.w)};
}

__global__ __launch_bounds__(256) void transpose_conv4(const float* __restrict__ W0,
                                                       const float* __restrict__ W1,
                                                       const float* __restrict__ W2,
                                                       const float* __restrict__ W3) {
    __shared__ float t[32][33];
    const int z = blockIdx.z;
    const float* src = (z == 0) ? W0 : (z == 1) ? W1 : (z == 2) ? W2 : W3;
    __half* dst = (z < 3) ? (g_wf + (size_t)z * DIM * DIM) : g_wof;

    const int bx = blockIdx.x * 32;
    const int by = blockIdx.y * 32;
    const int x = threadIdx.x, y0 = threadIdx.y;
#pragma unroll
    for (int i = 0; i < 32; i += 8)
        t[y0 + i][x] = src[(by + y0 + i) * DIM + bx + x];
    __syncthreads();
#pragma unroll
    for (int i = 0; i < 32; i += 8) {
        float v = t[x][y0 + i];
        dst[(bx + y0 + i) * DIM + by + x] = __float2half_rn(v);
    }
}

// ---------------------------------------------------------------------------
// Plain fp16 GEMM, cp.async 3-stage, BK=32, 2 CTAs/SM.
// MODE 0: QKV epilogue (Q pre-scaled, K, V^T). MODE 1: out proj + bias.
// ---------------------------------------------------------------------------
#define GBK    32
#define GSTR   40
#define GARR   (128 * GSTR)            // 5120 elems
#define GSTAGE (2 * GARR)              // 10240 elems
#define GSM_BYTES (3 * GSTAGE * 2)     // 61440

template <int MODE, int RB>
__global__ __launch_bounds__(256, 2) void gemm_f16(
    const __half* __restrict__ A, const __half* __restrict__ B,
    float* __restrict__ outp, const float* __restrict__ bo) {
    extern __shared__ __half smq[];

    const int tid  = threadIdx.x;
    const int lane = tid & 31;
    const int wid  = tid >> 5;
    const int wm   = wid & 1;
    const int wn   = wid >> 1;
    const int col0 = blockIdx.x * 128;

    const __half* pB = B + (size_t)col0 * DIM;
    const uint32_t sbase = smem_u32(smq);

    const int a_row = (lane & 15);
    const int a_kof = (lane >> 4) << 3;
    const int b_rof = ((lane >> 4) << 3) + (lane & 7);
    const int b_kof = ((lane >> 3) & 1) << 3;

    for (int rb = 0; rb < RB; ++rb) {
        const int row0 = (blockIdx.y * RB + rb) * 128;
        const __half* pA = A + (size_t)row0 * DIM;

        float acc[4][4][4];
#pragma unroll
        for (int i = 0; i < 4; i++)
#pragma unroll
            for (int j = 0; j < 4; j++)
#pragma unroll
                for (int q = 0; q < 4; q++) acc[i][j][q] = 0.0f;

        auto issue = [&](int c, int st) {
            const int k0 = c * GBK;
            const uint32_t sst = sbase + (uint32_t)(st * GSTAGE) * 2;
#pragma unroll
            for (int it = 0; it < 2; ++it) {
                const int lin = it * 256 + tid;
                const int rr = lin >> 2;
                const int cg = (lin & 3) * 8;
                const uint32_t so = (uint32_t)(rr * GSTR + cg) * 2;
                const size_t go = (size_t)rr * DIM + k0 + cg;
                cp16(sst + so,                      pA + go);
                cp16(sst + (uint32_t)GARR * 2 + so, pB + go);
            }
            cp_commit();
        };

        issue(0, 0);
        issue(1, 1);

        const int NC = DIM / GBK;   // 32
        for (int c = 0; c < NC; ++c) {
            if (c + 1 < NC) cp_wait1(); else cp_wait0();
            __syncthreads();
            if (c + 2 < NC) issue(c + 2, (c + 2) % 3);

            const uint32_t sA = sbase + (uint32_t)((c % 3) * GSTAGE) * 2;
            const uint32_t sB = sA + (uint32_t)GARR * 2;

#pragma unroll
            for (int ks = 0; ks < GBK / 16; ++ks) {
                uint32_t bf[2][4];
#pragma unroll
                for (int p = 0; p < 2; ++p) {
                    const uint32_t off =
                        (uint32_t)(((wn * 32 + p * 16 + b_rof) * GSTR + ks * 16 + b_kof) * 2);
                    ldsm4(bf[p][0], bf[p][1], bf[p][2], bf[p][3], sB + off);
                }
#pragma unroll
                for (int mi = 0; mi < 4; ++mi) {
                    uint32_t af[4];
                    const uint32_t off =
                        (uint32_t)(((wm * 64 + mi * 16 + a_row) * GSTR + ks * 16 + a_kof) * 2);
                    ldsm4(af[0], af[1], af[2], af[3], sA + off);
#pragma unroll
                    for (int p = 0; p < 2; ++p)
#pragma unroll
                        for (int q = 0; q < 2; ++q)
                            mma16816h(acc[mi][p * 2 + q], af, &bf[p][q * 2]);
                }
            }
        }

#pragma unroll
        for (int mi = 0; mi < 4; ++mi) {
#pragma unroll
            for (int nj = 0; nj < 4; ++nj) {
                const int r = row0 + wm * 64 + mi * 16 + (lane >> 2);
                const int cgl = col0 + wn * 32 + nj * 8 + (lane & 3) * 2;
#pragma unroll
                for (int half = 0; half < 2; ++half) {
                    const int rr = r + half * 8;
                    float v0 = acc[mi][nj][half * 2 + 0];
                    float v1 = acc[mi][nj][half * 2 + 1];
                    if (MODE == 0) {
                        const int b_ = rr >> 11, n = rr & 2047;
                        const int wsel = cgl >> 10;
                        const int c1 = cgl & 1023;
                        const int h = c1 >> 6, d0 = c1 & 63;
                        if (wsel == 0) {
                            const size_t o = ((size_t)(b_ * HEADS + h) * SEQ + n) * HD + d0;
                            *(__half2*)(g_Qf + o) = {__float2half_rn(v0 * SCALE_Q),
                                                     __float2half_rn(v1 * SCALE_Q)};
                        } else if (wsel == 1) {
                            const size_t o = ((size_t)(b_ * HEADS + h) * SEQ + n) * HD + d0;
                            *(__half2*)(g_Kf + o) = {__float2half_rn(v0), __float2half_rn(v1)};
                        } else {
                            const size_t o = ((size_t)(b_ * HEADS + h) * HD + d0) * SEQ + n;
                            g_Vf[o]       = __float2half_rn(v0);
                            g_Vf[o + SEQ] = __float2half_rn(v1);
                        }
                    } else {
                        *(float2*)(outp + (size_t)rr * DIM + cgl) =
                            make_float2(v0 + bo[cgl], v1 + bo[cgl + 1]);
                    }
                }
            }
        }
        if (rb + 1 < RB) __syncthreads();
    }
}

// ---------------------------------------------------------------------------
// Flash attention, plain fp16 (Q·K, P·V single products), Q frags in registers.
// 256 thr, 8 warps x 16 q-rows, KV chunk 64, cp.async 2-stage, 2 CTAs/SM.
// ---------------------------------------------------------------------------
#define ASTR   72
#define AQ_ELE (128 * ASTR)            // 9216 (Q staging)
#define KV_AR  (64 * ASTR)             // 4608 per K / V array
#define AST_EL (2 * KV_AR)             // 9216 per stage
#define A_KV0  AQ_ELE                  // KV stages start after Q staging
#define A_TOTAL ((A_KV0 + 2 * AST_EL) * 2)   // 55296 bytes

__global__ __launch_bounds__(256, 2) void attn_mma() {
    extern __shared__ __half sma[];

    const int bh   = blockIdx.y;
    const int rblk = blockIdx.x;
    const int tid  = threadIdx.x;
    const int lane = tid & 31;
    const int wid  = tid >> 5;
    const int q0   = wid * 16;

    const size_t qbase = ((size_t)bh * SEQ + rblk * 128) * HD;
    const size_t kbase = (size_t)bh * SEQ * HD;
    const size_t vbase = (size_t)bh * HD * SEQ;

    const uint32_t sbase = smem_u32(sma);

    const int a_row = lane & 15;
    const int a_kof = (lane >> 4) << 3;
    const int b_rof = ((lane >> 4) << 3) + (lane & 7);
    const int b_kof = ((lane >> 3) & 1) << 3;

    // Stage Q once, then hold fragments in registers
#pragma unroll
    for (int it = 0; it < 4; ++it) {
        const int lin = it * 256 + tid;
        const int r = lin >> 3, d = (lin & 7) * 8;
        cp16(sbase + (uint32_t)(r * ASTR + d) * 2, g_Qf + qbase + (size_t)r * HD + d);
    }
    cp_commit();
    cp_wait0();
    __syncthreads();

    uint32_t qf[4][4];
#pragma unroll
    for (int ks = 0; ks < 4; ++ks) {
        const uint32_t off = (uint32_t)(((q0 + a_row) * ASTR + ks * 16 + a_kof) * 2);
        ldsm4(qf[ks][0], qf[ks][1], qf[ks][2], qf[ks][3], sbase + off);
    }

    auto issue_kv = [&](int chunk, int st) {
        const int c0 = chunk * 64;
        const uint32_t skv = sbase + (uint32_t)(A_KV0 + st * AST_EL) * 2;
#pragma unroll
        for (int it = 0; it < 2; ++it) {
            const int lin = it * 256 + tid;
            const int r = lin >> 3, d = (lin & 7) * 8;
            const uint32_t so = (uint32_t)(r * ASTR + d) * 2;
            cp16(skv + so,                        g_Kf + kbase + (size_t)(c0 + r) * HD + d);
            cp16(skv + (uint32_t)KV_AR * 2 + so,  g_Vf + vbase + (size_t)r * SEQ + c0 + d);
        }
        cp_commit();
    };

    issue_kv(0, 0);

    float acc_o[8][4];
#pragma unroll
    for (int j = 0; j < 8; j++)
#pragma unroll
        for (int q = 0; q < 4; q++) acc_o[j][q] = 0.0f;
    float mi[2] = {-1e30f, -1e30f}, li[2] = {0.0f, 0.0f};

    const int NC = SEQ / 64;   // 32
    for (int c = 0; c < NC; ++c) {
        const int st = c & 1;
        cp_wait0();
        __syncthreads();
        if (c + 1 < NC) issue_kv(c + 1, st ^ 1);

        const uint32_t skv = sbase + (uint32_t)(A_KV0 + st * AST_EL) * 2;
        const uint32_t uK = skv;
        const uint32_t uV = skv + (uint32_t)KV_AR * 2;

        // --- S = Q K^T ---
        float acc_s[8][4];
#pragma unroll
        for (int j = 0; j < 8; j++)
#pragma unroll
            for (int q = 0; q < 4; q++) acc_s[j][q] = 0.0f;

#pragma unroll
        for (int ks = 0; ks < 4; ++ks) {
#pragma unroll
            for (int p = 0; p < 4; ++p) {
                uint32_t kf[4];
                const uint32_t off = (uint32_t)(((p * 16 + b_rof) * ASTR + ks * 16 + b_kof) * 2);
                ldsm4(kf[0], kf[1], kf[2], kf[3], uK + off);
#pragma unroll
                for (int q = 0; q < 2; ++q)
                    mma16816h(acc_s[p * 2 + q], qf[ks], &kf[q * 2]);
            }
        }

        // --- online softmax in exp2 domain ---
#pragma unroll
        for (int half = 0; half < 2; ++half) {
            float rmax = -1e30f;
#pragma unroll
            for (int nj = 0; nj < 8; ++nj)
#pragma unroll
                for (int t = 0; t < 2; ++t)
                    rmax = fmaxf(rmax, acc_s[nj][half * 2 + t]);
            rmax = fmaxf(rmax, __shfl_xor_sync(0xffffffffu, rmax, 1));
            rmax = fmaxf(rmax, __shfl_xor_sync(0xffffffffu, rmax, 2));
            const float mn = fmaxf(mi[half], rmax);
            float rsum = 0.0f;
#pragma unroll
            for (int nj = 0; nj < 8; ++nj)
#pragma unroll
                for (int t = 0; t < 2; ++t) {
                    const float e = ex2(acc_s[nj][half * 2 + t] - mn);
                    acc_s[nj][half * 2 + t] = e;
                    rsum += e;
                }
            rsum += __shfl_xor_sync(0xffffffffu, rsum, 1);
            rsum += __shfl_xor_sync(0xffffffffu, rsum, 2);
            const float alpha = ex2(mi[half] - mn);
            li[half] = li[half] * alpha + rsum;
            mi[half] = mn;
#pragma unroll
            for (int nj = 0; nj < 8; ++nj)
#pragma unroll
                for (int t = 0; t < 2; ++t) acc_o[nj][half * 2 + t] *= alpha;
        }

        // --- O += P V ---
#pragma unroll
        for (int ks = 0; ks < 4; ++ks) {
            uint32_t pf[4];
            pf[0] = pack_h2(acc_s[2 * ks][0],     acc_s[2 * ks][1]);
            pf[1] = pack_h2(acc_s[2 * ks][2],     acc_s[2 * ks][3]);
            pf[2] = pack_h2(acc_s[2 * ks + 1][0], acc_s[2 * ks + 1][1]);
            pf[3] = pack_h2(acc_s[2 * ks + 1][2], acc_s[2 * ks + 1][3]);
#pragma unroll
            for (int p = 0; p < 4; ++p) {
                uint32_t vf[4];
                const uint32_t off = (uint32_t)(((p * 16 + b_rof) * ASTR + ks * 16 + b_kof) * 2);
                ldsm4(vf[0], vf[1], vf[2], vf[3], uV + off);
#pragma unroll
                for (int q = 0; q < 2; ++q)
                    mma16816h(acc_o[p * 2 + q], pf, &vf[q * 2]);
            }
        }
    }

    // Epilogue: normalize, write fp16 O
    const int b_ = bh >> 4, h = bh & 15;
#pragma unroll
    for (int half = 0; half < 2; ++half) {
        const float inv = 1.0f / li[half];
        const int row = rblk * 128 + q0 + (lane >> 2) + half * 8;
        const size_t mrow = ((size_t)b_ * SEQ + row) * DIM + h * HD;
#pragma unroll
        for (int nj = 0; nj < 8; ++nj) {
            const int cc = nj * 8 + (lane & 3) * 2;
            *(__half2*)(g_of + mrow + cc) = {
                __float2half_rn(acc_o[nj][half * 2 + 0] * inv),
                __float2half_rn(acc_o[nj][half * 2 + 1] * inv)};
        }
    }
}

// ---------------------------------------------------------------------------

extern "C" void kernel_launch(void* const* d_in, const int* in_sizes, int n_in,
                              void* d_out, int out_size) {
    (void)in_sizes; (void)n_in; (void)out_size;
    const float* x  = (const float*)d_in[0];
    const float* Wq = (const float*)d_in[1];
    const float* Wk = (const float*)d_in[2];
    const float* Wv = (const float*)d_in[3];
    const float* Wo = (const float*)d_in[4];
    const float* bo = (const float*)d_in[5];
    float* out = (float*)d_out;

    cudaFuncSetAttribute((const void*)gemm_f16<0, 1>,
                         cudaFuncAttributeMaxDynamicSharedMemorySize, GSM_BYTES);
    cudaFuncSetAttribute((const void*)gemm_f16<1, 2>,
                         cudaFuncAttributeMaxDynamicSharedMemorySize, GSM_BYTES);
    cudaFuncSetAttribute((const void*)attn_mma,
                         cudaFuncAttributeMaxDynamicSharedMemorySize, A_TOTAL);

    __half *xf, *wf, *wof, *of;
    cudaGetSymbolAddress((void**)&xf,  g_xf);
    cudaGetSymbolAddress((void**)&wf,  g_wf);
    cudaGetSymbolAddress((void**)&wof, g_wof);
    cudaGetSymbolAddress((void**)&of,  g_of);

    conv_x_kernel<<<MROWS * DIM / 1024, 256>>>(x);
    transpose_conv4<<<dim3(32, 32, 4), dim3(32, 8)>>>(Wq, Wk, Wv, Wo);

    gemm_f16<0, 1><<<dim3(24, 64), 256, GSM_BYTES>>>(xf, wf, nullptr, nullptr);
    attn_mma<<<dim3(16, 64), 256, A_TOTAL>>>();
    gemm_f16<1, 2><<<dim3(8, 32), 256, GSM_BYTES>>>(of, wof, out, bo);
}